// round 3
// baseline (speedup 1.0000x reference)
#include <cuda_runtime.h>
#include <math.h>
#include <stdint.h>
#include <stddef.h>

// ---- problem constants ----
#define HD  256      // HIDDEN_DIM
#define ZD  64       // Z_DIM
#define BB  8        // batch
#define SL  2048     // SRC_LEN
#define QT  16       // queries per block in k_attn
#define KC  256      // key chunk in k_attn
#define CAP 128      // per-row nonzero-attn list capacity
#define SKIP_T (-88.0f)

// ---- device scratch (no allocation allowed) ----
__device__ float g_venc[BB][HD];     // v_enc per batch
__device__ float g_qenc[BB][HD];     // q_enc per batch (only used to form u)
__device__ float g_u[BB][ZD];        // u_b = Wk_z q_enc
__device__ float g_zsum[BB][ZD];     // sum_k z[b,k,:]
__device__ float g_M[ZD][ZD];        // Wq_z Wk_z^T
__device__ float g_wT[BB * ZD * SL]; // w transposed: [b][d][key], w = (M z_k)/16
__device__ float g_c[BB][SL];        // c_k = (u_b . z_k)/16

// =================== kernel 1: per-batch constants + M =====================
// grid = 12 (8 batch blocks + 4 M-tile blocks), 256 threads
__global__ void k_prep(const float* __restrict__ ehs,
                       const float* __restrict__ z,
                       const float* __restrict__ wq,
                       const float* __restrict__ wk,
                       const float* __restrict__ wv) {
    int t = threadIdx.x;
    if (blockIdx.x < BB) {
        int b = blockIdx.x;
        __shared__ float enc[HD];
        __shared__ float qe[HD];
        __shared__ float zs[4][ZD];
        // enc = sum over 2 directions
        enc[t] = ehs[b * HD + t] + ehs[BB * HD + b * HD + t];
        __syncthreads();
        float aq = 0.f, av = 0.f;
        for (int d = 0; d < HD; d++) {
            float ev = enc[d];
            aq += ev * wq[d * HD + t];
            av += ev * wv[d * HD + t];
        }
        qe[t] = aq;
        g_qenc[b][t] = aq;
        g_venc[b][t] = av;
        __syncthreads();
        if (t < ZD) {
            float au = 0.f;
            for (int h = 0; h < HD; h++) au += qe[h] * wk[(HD + t) * HD + h];
            g_u[b][t] = au;
        }
        // zsum[b][e]
        int e = t & 63, part = t >> 6;
        const float* zp = z + (size_t)b * SL * ZD;
        float s = 0.f;
        for (int k = part * 512; k < part * 512 + 512; k++)
            s += zp[(size_t)k * ZD + e];
        zs[part][e] = s;
        __syncthreads();
        if (t < ZD) g_zsum[b][t] = zs[0][t] + zs[1][t] + zs[2][t] + zs[3][t];
    } else {
        // M[d][e] = sum_h Wq_z[d,h] * Wk_z[e,h]
        int i = blockIdx.x - BB;    // tile of 16 d-rows
        int e = t & 63, dl = t >> 6;
        for (int j = 0; j < 4; j++) {
            int d = i * 16 + dl * 4 + j;
            const float* qrow = wq + (size_t)(HD + d) * HD;
            const float* krow = wk + (size_t)(HD + e) * HD;
            float acc = 0.f;
            for (int h = 0; h < HD; h++) acc += qrow[h] * krow[h];
            g_M[d][e] = acc;
        }
    }
}

// ===== kernel 2: wT[b,d,k] = (M z_k)[d]/16, c[b,k] = (u_b.z_k)/16 ==========
// grid = 128 blocks * 128 threads (1 key/thread)
__global__ void k_wc(const float* __restrict__ z) {
    __shared__ float Ms[ZD][ZD];
    __shared__ float us[ZD];
    int t = threadIdx.x;
    int b = blockIdx.x >> 4;
    int k0 = (blockIdx.x & 15) * 128;
    for (int i = t; i < ZD * ZD / 4; i += 128)
        ((float4*)Ms)[i] = ((const float4*)g_M)[i];
    if (t < ZD) us[t] = g_u[b][t];
    __syncthreads();

    int key = k0 + t;
    const float4* zp4 = (const float4*)(z + ((size_t)b * SL + key) * ZD);
    float zr[ZD];
#pragma unroll
    for (int i = 0; i < ZD / 4; i++) {
        float4 v = zp4[i];
        zr[4 * i + 0] = v.x; zr[4 * i + 1] = v.y;
        zr[4 * i + 2] = v.z; zr[4 * i + 3] = v.w;
    }
    const float inv_t = 0.0625f;  // 1/sqrt(HD)
    float cacc = 0.f;
#pragma unroll
    for (int e = 0; e < ZD; e++) cacc += zr[e] * us[e];
    g_c[b][key] = cacc * inv_t;

    float* wt = g_wT + (size_t)b * ZD * SL;
#pragma unroll
    for (int d4 = 0; d4 < ZD / 4; d4++) {
        float a0 = 0.f, a1 = 0.f, a2 = 0.f, a3 = 0.f;
#pragma unroll
        for (int e4 = 0; e4 < ZD / 4; e4++) {
            float4 m0 = ((const float4*)&Ms[4 * d4 + 0][0])[e4];
            float4 m1 = ((const float4*)&Ms[4 * d4 + 1][0])[e4];
            float4 m2 = ((const float4*)&Ms[4 * d4 + 2][0])[e4];
            float4 m3 = ((const float4*)&Ms[4 * d4 + 3][0])[e4];
            float z0 = zr[4 * e4 + 0], z1 = zr[4 * e4 + 1];
            float z2 = zr[4 * e4 + 2], z3 = zr[4 * e4 + 3];
            a0 += m0.x * z0 + m0.y * z1 + m0.z * z2 + m0.w * z3;
            a1 += m1.x * z0 + m1.y * z1 + m1.z * z2 + m1.w * z3;
            a2 += m2.x * z0 + m2.y * z1 + m2.z * z2 + m2.w * z3;
            a3 += m3.x * z0 + m3.y * z1 + m3.z * z2 + m3.w * z3;
        }
        wt[(size_t)(4 * d4 + 0) * SL + key] = a0 * inv_t;
        wt[(size_t)(4 * d4 + 1) * SL + key] = a1 * inv_t;
        wt[(size_t)(4 * d4 + 2) * SL + key] = a2 * inv_t;
        wt[(size_t)(4 * d4 + 3) * SL + key] = a3 * inv_t;
    }
}

// =================== kernel 3: scores + softmax + output ===================
struct __align__(16) AttnSmem {
    float sc[QT][SL];        // 131072 B: score tile -> then exp values
    float w[ZD][KC];         //  65536 B: w chunk, d-major
    float zq[QT][ZD];        //   4096 B
    float yT[ZD][QT];        //   4096 B: y transposed [e][q]
    float pv[QT][CAP];       //   8192 B: nonzero exp values
    int   kv[QT][CAP];       //   8192 B: nonzero key indices
    int   cnt[QT];
    float invZ_s[QT];
    int   mskd[QT];
};                            // total 221,632 B < 227 KB

__global__ void __launch_bounds__(256, 1)
k_attn(const float* __restrict__ z, const float* __restrict__ wv,
       const int* __restrict__ mask, float* __restrict__ outp,
       float* __restrict__ attnp) {
    extern __shared__ char smraw[];
    AttnSmem& s = *reinterpret_cast<AttnSmem*>(smraw);
    int t = threadIdx.x;
    int b = blockIdx.x >> 7;           // 128 q-tiles per batch
    int q0 = (blockIdx.x & 127) * QT;

    // load z_q tile [QT][ZD]
    {
        int qr = t >> 4, f4 = t & 15;
        float4 v = *((const float4*)(z + ((size_t)b * SL + q0 + qr) * ZD) + f4);
        *((float4*)&s.zq[qr][0] + f4) = v;
    }

    int kq = t & 63, qg = t >> 6;
    int kk = kq * 4;
    const float* gwT = g_wT + (size_t)b * ZD * SL;

    // ---- score GEMM: sc[q][k] = zq . w_k + c_k ----
    for (int ch = 0; ch < SL / KC; ch++) {
        int k0 = ch * KC;
        __syncthreads();   // protect previous chunk's w reads / zq store
        // load w chunk [64][256] (d-major rows, contiguous from gwT)
#pragma unroll
        for (int i = 0; i < 16; i++) {
            int idx = t + i * 256;
            int e = idx >> 6, f4 = idx & 63;
            float4 v = *((const float4*)(gwT + (size_t)e * SL + k0) + f4);
            *((float4*)&s.w[e][0] + f4) = v;
        }
        __syncthreads();

        float4 cv = *((const float4*)&g_c[b][k0 + kk]);
        float acc[4][4];
#pragma unroll
        for (int i = 0; i < 4; i++) {
            acc[i][0] = cv.x; acc[i][1] = cv.y; acc[i][2] = cv.z; acc[i][3] = cv.w;
        }
#pragma unroll
        for (int e4 = 0; e4 < 16; e4++) {
            const int e = e4 * 4;
            float av[4][4], bv[4][4];
#pragma unroll
            for (int i = 0; i < 4; i++) {
                float4 a = *(const float4*)&s.zq[4 * qg + i][e];
                av[i][0] = a.x; av[i][1] = a.y; av[i][2] = a.z; av[i][3] = a.w;
            }
#pragma unroll
            for (int l = 0; l < 4; l++) {
                float4 w4 = *(const float4*)&s.w[e + l][kk];
                bv[l][0] = w4.x; bv[l][1] = w4.y; bv[l][2] = w4.z; bv[l][3] = w4.w;
            }
#pragma unroll
            for (int i = 0; i < 4; i++)
#pragma unroll
                for (int l = 0; l < 4; l++)
#pragma unroll
                    for (int j = 0; j < 4; j++)
                        acc[i][j] += av[i][l] * bv[l][j];
        }
#pragma unroll
        for (int i = 0; i < 4; i++)
            *((float4*)&s.sc[4 * qg + i][k0 + kk]) =
                make_float4(acc[i][0], acc[i][1], acc[i][2], acc[i][3]);
    }
    __syncthreads();

    // ---- per-row softmax (warp w owns rows 2w, 2w+1) ----
    int w_id = t >> 5, lane = t & 31;
    const float* zb = z + (size_t)b * SL * ZD;

    for (int rr = 0; rr < 2; rr++) {
        int r = w_id * 2 + rr;
        int msk = mask[b * SL + q0 + r];
        if (lane == 0) { s.mskd[r] = msk; s.cnt[r] = 0; }
        __syncwarp();

        float iz = 0.f;
        if (msk != 0) {
            const float4* row4 = (const float4*)&s.sc[r][0];
            float4* row4w = (float4*)&s.sc[r][0];
            // row max
            float mx = -3.4e38f;
#pragma unroll
            for (int i = 0; i < 16; i++) {
                float4 v = row4[i * 32 + lane];
                mx = fmaxf(mx, fmaxf(fmaxf(v.x, v.y), fmaxf(v.z, v.w)));
            }
#pragma unroll
            for (int o = 16; o; o >>= 1) mx = fmaxf(mx, __shfl_xor_sync(~0u, mx, o));
            // exp + Z + sparse list (window-voted skip)
            float Zp = 0.f;
            for (int i = 0; i < 16; i++) {
                int idx = i * 32 + lane;
                float4 v = row4[idx];
                float d0 = v.x - mx, d1 = v.y - mx, d2 = v.z - mx, d3 = v.w - mx;
                float dm = fmaxf(fmaxf(d0, d1), fmaxf(d2, d3));
                unsigned bal = __ballot_sync(~0u, dm >= SKIP_T);
                if (bal == 0) { row4w[idx] = make_float4(0.f, 0.f, 0.f, 0.f); continue; }
                float p0 = __expf(d0), p1 = __expf(d1);
                float p2 = __expf(d2), p3 = __expf(d3);
                row4w[idx] = make_float4(p0, p1, p2, p3);
                Zp += (p0 + p1) + (p2 + p3);
                int kb = idx * 4;
                if (p0 > 0.f) { int p = atomicAdd(&s.cnt[r], 1); if (p < CAP) { s.kv[r][p] = kb + 0; s.pv[r][p] = p0; } }
                if (p1 > 0.f) { int p = atomicAdd(&s.cnt[r], 1); if (p < CAP) { s.kv[r][p] = kb + 1; s.pv[r][p] = p1; } }
                if (p2 > 0.f) { int p = atomicAdd(&s.cnt[r], 1); if (p < CAP) { s.kv[r][p] = kb + 2; s.pv[r][p] = p2; } }
                if (p3 > 0.f) { int p = atomicAdd(&s.cnt[r], 1); if (p < CAP) { s.kv[r][p] = kb + 3; s.pv[r][p] = p3; } }
            }
#pragma unroll
            for (int o = 16; o; o >>= 1) Zp += __shfl_xor_sync(~0u, Zp, o);
            iz = 1.0f / Zp;
            if (lane == 0) s.invZ_s[r] = iz;
        }
        __syncwarp();

        // attn write + y accumulation
        float y0 = 0.f, y1 = 0.f;
        if (msk == 0) {
            if (attnp) {
                const float u = 1.0f / 2048.0f;
                float4 u4 = make_float4(u, u, u, u);
                float4* ap = (float4*)(attnp + (size_t)(b * SL + q0 + r) * SL);
#pragma unroll
                for (int i = 0; i < 16; i++) ap[i * 32 + lane] = u4;
            }
            y0 = g_zsum[b][lane] * (1.0f / 2048.0f);
            y1 = g_zsum[b][lane + 32] * (1.0f / 2048.0f);
        } else {
            if (attnp) {
                const float4* row4 = (const float4*)&s.sc[r][0];
                float4* ap = (float4*)(attnp + (size_t)(b * SL + q0 + r) * SL);
#pragma unroll
                for (int i = 0; i < 16; i++) {
                    float4 p = row4[i * 32 + lane];
                    ap[i * 32 + lane] = make_float4(p.x * iz, p.y * iz, p.z * iz, p.w * iz);
                }
            }
            int cnt = s.cnt[r];
            if (cnt <= CAP) {
                for (int i = 0; i < cnt; i++) {
                    float a = s.pv[r][i] * iz;
                    int k = s.kv[r][i];
                    y0 += a * zb[(size_t)k * ZD + lane];
                    y1 += a * zb[(size_t)k * ZD + lane + 32];
                }
            } else {  // extremely rare dense fallback
                for (int k = 0; k < SL; k++) {
                    float p = s.sc[r][k];
                    if (p != 0.f) {
                        float a = p * iz;
                        y0 += a * zb[(size_t)k * ZD + lane];
                        y1 += a * zb[(size_t)k * ZD + lane + 32];
                    }
                }
            }
        }
        s.yT[lane][r] = y0;
        s.yT[lane + 32][r] = y1;
    }
    __syncthreads();

    // ---- output epilogue: out[q][h] = v_enc[h] + sum_e y[q][e] Wv_z[e][h] ----
    if (outp) {
        float acc[QT];
        float ve = g_venc[b][t];
#pragma unroll
        for (int q = 0; q < QT; q++) acc[q] = ve;
#pragma unroll 4
        for (int e = 0; e < ZD; e++) {
            float wvv = wv[(size_t)(HD + e) * HD + t];
            const float4* yr = (const float4*)&s.yT[e][0];
            float4 ya = yr[0], yb = yr[1], yc = yr[2], yd = yr[3];
            acc[0]  += ya.x * wvv; acc[1]  += ya.y * wvv;
            acc[2]  += ya.z * wvv; acc[3]  += ya.w * wvv;
            acc[4]  += yb.x * wvv; acc[5]  += yb.y * wvv;
            acc[6]  += yb.z * wvv; acc[7]  += yb.w * wvv;
            acc[8]  += yc.x * wvv; acc[9]  += yc.y * wvv;
            acc[10] += yc.z * wvv; acc[11] += yc.w * wvv;
            acc[12] += yd.x * wvv; acc[13] += yd.y * wvv;
            acc[14] += yd.z * wvv; acc[15] += yd.w * wvv;
        }
#pragma unroll
        for (int q = 0; q < QT; q++)
            outp[((size_t)b * SL + q0 + q) * HD + t] = acc[q];
    }
}

// ============================== launch =====================================
extern "C" void kernel_launch(void* const* d_in, const int* in_sizes, int n_in,
                              void* d_out, int out_size) {
    const float* ehs  = (const float*)d_in[0];
    // d_in[1] = decoder_hidden_state (unused by reference)
    const float* z    = (const float*)d_in[2];
    const int*   mask = (const int*)d_in[3];
    const float* wq   = (const float*)d_in[4];
    const float* wk   = (const float*)d_in[5];
    const float* wv   = (const float*)d_in[6];

    const long OUT_N = (long)BB * SL * HD;   //  4,194,304
    const long ATT_N = (long)BB * SL * SL;   // 33,554,432
    float* o = (float*)d_out;
    float* outp = nullptr;
    float* attnp = nullptr;
    if ((long)out_size >= OUT_N + ATT_N) { outp = o; attnp = o + OUT_N; }
    else if ((long)out_size == ATT_N)    { attnp = o; }
    else                                 { outp = o; }

    cudaFuncSetAttribute(k_attn, cudaFuncAttributeMaxDynamicSharedMemorySize,
                         (int)sizeof(AttnSmem));

    k_prep<<<BB + 4, 256>>>(ehs, z, wq, wk, wv);
    k_wc<<<128, 128>>>(z);
    k_attn<<<BB * (SL / QT), 256, sizeof(AttnSmem)>>>(z, wv, mask, outp, attnp);
}

// round 4
// speedup vs baseline: 1.2135x; 1.2135x over previous
#include <cuda_runtime.h>
#include <math.h>
#include <stdint.h>
#include <stddef.h>

// ---- problem constants ----
#define HD  256      // HIDDEN_DIM
#define ZD  64       // Z_DIM
#define BB  8        // batch
#define SL  2048     // SRC_LEN
#define QT  16       // queries per block in k_attn
#define KC  256      // key chunk in k_attn
#define CAP 128      // per-row nonzero-attn list capacity
#define SKIP_T (-88.0f)
#define KZP 260      // padded smem row (floats), 16B-aligned

// ---- device scratch (no allocation allowed) ----
__device__ float g_venc[BB][HD];     // v_enc per batch
__device__ float g_qenc[BB][HD];     // q_enc per batch
__device__ float g_u[BB][ZD];        // u_b = Wk_z q_enc
__device__ float g_zsum[BB][ZD];     // sum_k z[b,k,:]
__device__ float g_M[ZD][ZD];        // Wq_z Wk_z^T
__device__ float g_wT[BB * ZD * SL]; // w transposed: [b][d][key], w = (M z_k)/16
__device__ float g_c[BB][SL];        // c_k = (u_b . z_k)/16

// ---- packed fp32x2 helpers ----
__device__ __forceinline__ void fma2(unsigned long long& d,
                                     unsigned long long a,
                                     unsigned long long b) {
    asm("fma.rn.f32x2 %0, %1, %2, %0;" : "+l"(d) : "l"(a), "l"(b));
}
__device__ __forceinline__ unsigned long long dup2(float x) {
    unsigned long long r;
    asm("mov.b64 %0, {%1, %1};" : "=l"(r) : "f"(x));
    return r;
}

// ============ kernel 1a: per-batch enc sums, qenc/venc, zsum ===============
// grid = 8 (one per batch), 256 threads
__global__ void k_prep1(const float* __restrict__ ehs,
                        const float* __restrict__ z,
                        const float* __restrict__ wq,
                        const float* __restrict__ wv) {
    __shared__ float enc[HD];
    __shared__ float zs[4][ZD];
    int t = threadIdx.x;
    int b = blockIdx.x;
    enc[t] = ehs[b * HD + t] + ehs[BB * HD + b * HD + t];
    __syncthreads();
    float aq = 0.f, av = 0.f;
#pragma unroll 8
    for (int d = 0; d < HD; d++) {
        float ev = enc[d];
        aq += ev * wq[d * HD + t];   // coalesced over t
        av += ev * wv[d * HD + t];
    }
    g_qenc[b][t] = aq;
    g_venc[b][t] = av;
    // zsum[b][e]
    int e = t & 63, part = t >> 6;
    const float* zp = z + (size_t)b * SL * ZD;
    float s = 0.f;
#pragma unroll 8
    for (int k = part * 512; k < part * 512 + 512; k++)
        s += zp[(size_t)k * ZD + e];
    zs[part][e] = s;
    __syncthreads();
    if (t < ZD) g_zsum[b][t] = zs[0][t] + zs[1][t] + zs[2][t] + zs[3][t];
}

// ============ kernel 1b: M = Wq_z Wk_z^T (smem-staged) + u ================
// grid = 4 (16 d-rows each), 256 threads, dynamic smem
struct __align__(16) P2Smem {
    float kz[ZD][KZP];   // 66560 B  Wk_z rows
    float qz[16][KZP];   // 16640 B  this block's Wq_z rows
    float qe[BB][HD];    //  8192 B  q_enc (block 0 only)
};                        // 91392 B

__global__ void k_prep2(const float* __restrict__ wq,
                        const float* __restrict__ wk) {
    extern __shared__ char smraw[];
    P2Smem& s = *reinterpret_cast<P2Smem*>(smraw);
    int t = threadIdx.x;
    int i = blockIdx.x;
    // load Wk_z (64 rows x 256) coalesced: 4 rows per sweep
#pragma unroll
    for (int r = 0; r < ZD; r += 4) {
        int e = r + (t >> 6), f4 = t & 63;
        float4 v = *((const float4*)(wk + (size_t)(HD + e) * HD) + f4);
        *((float4*)&s.kz[e][0] + f4) = v;
    }
    // load this block's 16 Wq_z rows
#pragma unroll
    for (int r = 0; r < 16; r += 4) {
        int dl = r + (t >> 6), f4 = t & 63;
        float4 v = *((const float4*)(wq + (size_t)(HD + i * 16 + dl) * HD) + f4);
        *((float4*)&s.qz[dl][0] + f4) = v;
    }
    __syncthreads();

    int e = t & 63, jg = t >> 6;
    float a0 = 0.f, a1 = 0.f, a2 = 0.f, a3 = 0.f;
#pragma unroll 8
    for (int h4 = 0; h4 < HD / 4; h4++) {
        float4 kv = *((const float4*)&s.kz[e][0] + h4);
        float4 q0 = *((const float4*)&s.qz[jg * 4 + 0][0] + h4);
        float4 q1 = *((const float4*)&s.qz[jg * 4 + 1][0] + h4);
        float4 q2 = *((const float4*)&s.qz[jg * 4 + 2][0] + h4);
        float4 q3 = *((const float4*)&s.qz[jg * 4 + 3][0] + h4);
        a0 += q0.x * kv.x + q0.y * kv.y + q0.z * kv.z + q0.w * kv.w;
        a1 += q1.x * kv.x + q1.y * kv.y + q1.z * kv.z + q1.w * kv.w;
        a2 += q2.x * kv.x + q2.y * kv.y + q2.z * kv.z + q2.w * kv.w;
        a3 += q3.x * kv.x + q3.y * kv.y + q3.z * kv.z + q3.w * kv.w;
    }
    g_M[i * 16 + jg * 4 + 0][e] = a0;
    g_M[i * 16 + jg * 4 + 1][e] = a1;
    g_M[i * 16 + jg * 4 + 2][e] = a2;
    g_M[i * 16 + jg * 4 + 3][e] = a3;

    // block 0 also computes u[b][e] = q_enc[b] . Wk_z[e]
    if (i == 0) {
        for (int idx = t; idx < BB * HD; idx += 256)
            ((float*)s.qe)[idx] = ((const float*)g_qenc)[idx];
        __syncthreads();
#pragma unroll
        for (int bb2 = 0; bb2 < 2; bb2++) {
            int b = (t >> 6) + bb2 * 4;
            float au = 0.f;
#pragma unroll 8
            for (int h4 = 0; h4 < HD / 4; h4++) {
                float4 kv = *((const float4*)&s.kz[e][0] + h4);
                float4 qv = *((const float4*)&s.qe[b][0] + h4);
                au += qv.x * kv.x + qv.y * kv.y + qv.z * kv.z + qv.w * kv.w;
            }
            g_u[b][e] = au;
        }
    }
}

// ===== kernel 2: wT[b,d,k] = (M z_k)[d]/16, c[b,k] = (u_b.z_k)/16 ==========
// grid = 128 blocks * 128 threads (1 key/thread)
__global__ void k_wc(const float* __restrict__ z) {
    __shared__ float Ms[ZD][ZD];
    __shared__ float us[ZD];
    int t = threadIdx.x;
    int b = blockIdx.x >> 4;
    int k0 = (blockIdx.x & 15) * 128;
    for (int i = t; i < ZD * ZD / 4; i += 128)
        ((float4*)Ms)[i] = ((const float4*)g_M)[i];
    if (t < ZD) us[t] = g_u[b][t];
    __syncthreads();

    int key = k0 + t;
    const float4* zp4 = (const float4*)(z + ((size_t)b * SL + key) * ZD);
    float zr[ZD];
#pragma unroll
    for (int i = 0; i < ZD / 4; i++) {
        float4 v = zp4[i];
        zr[4 * i + 0] = v.x; zr[4 * i + 1] = v.y;
        zr[4 * i + 2] = v.z; zr[4 * i + 3] = v.w;
    }
    const float inv_t = 0.0625f;  // 1/sqrt(HD)
    float cacc = 0.f;
#pragma unroll
    for (int e = 0; e < ZD; e++) cacc += zr[e] * us[e];
    g_c[b][key] = cacc * inv_t;

    float* wt = g_wT + (size_t)b * ZD * SL;
#pragma unroll
    for (int d4 = 0; d4 < ZD / 4; d4++) {
        float a0 = 0.f, a1 = 0.f, a2 = 0.f, a3 = 0.f;
#pragma unroll
        for (int e4 = 0; e4 < ZD / 4; e4++) {
            float4 m0 = ((const float4*)&Ms[4 * d4 + 0][0])[e4];
            float4 m1 = ((const float4*)&Ms[4 * d4 + 1][0])[e4];
            float4 m2 = ((const float4*)&Ms[4 * d4 + 2][0])[e4];
            float4 m3 = ((const float4*)&Ms[4 * d4 + 3][0])[e4];
            float z0 = zr[4 * e4 + 0], z1 = zr[4 * e4 + 1];
            float z2 = zr[4 * e4 + 2], z3 = zr[4 * e4 + 3];
            a0 += m0.x * z0 + m0.y * z1 + m0.z * z2 + m0.w * z3;
            a1 += m1.x * z0 + m1.y * z1 + m1.z * z2 + m1.w * z3;
            a2 += m2.x * z0 + m2.y * z1 + m2.z * z2 + m2.w * z3;
            a3 += m3.x * z0 + m3.y * z1 + m3.z * z2 + m3.w * z3;
        }
        wt[(size_t)(4 * d4 + 0) * SL + key] = a0 * inv_t;
        wt[(size_t)(4 * d4 + 1) * SL + key] = a1 * inv_t;
        wt[(size_t)(4 * d4 + 2) * SL + key] = a2 * inv_t;
        wt[(size_t)(4 * d4 + 3) * SL + key] = a3 * inv_t;
    }
}

// =================== kernel 3: scores + softmax + output ===================
struct __align__(16) AttnSmem {
    float sc[QT][SL];        // 131072 B: score tile -> then exp values
    float w[ZD][KC];         //  65536 B: w chunk, d-major
    float zq[QT][ZD];        //   4096 B
    float yT[ZD][QT];        //   4096 B: y transposed [e][q]
    float pv[QT][CAP];       //   8192 B
    int   kv[QT][CAP];       //   8192 B
    int   cnt[QT];
    float invZ_s[QT];
    int   mskd[QT];
};                            // total ~221,632 B

__global__ void __launch_bounds__(256, 1)
k_attn(const float* __restrict__ z, const float* __restrict__ wv,
       const int* __restrict__ mask, float* __restrict__ outp,
       float* __restrict__ attnp) {
    extern __shared__ char smraw[];
    AttnSmem& s = *reinterpret_cast<AttnSmem*>(smraw);
    int t = threadIdx.x;
    int b = blockIdx.x >> 7;
    int q0 = (blockIdx.x & 127) * QT;

    // load z_q tile [QT][ZD]
    {
        int qr = t >> 4, f4 = t & 15;
        float4 v = *((const float4*)(z + ((size_t)b * SL + q0 + qr) * ZD) + f4);
        *((float4*)&s.zq[qr][0] + f4) = v;
    }

    int kq = t & 63, qg = t >> 6;
    int kk = kq * 4;
    const float* gwT = g_wT + (size_t)b * ZD * SL;

    // ---- score GEMM: sc[q][k] = zq . w_k + c_k  (packed f32x2 FMA) ----
    for (int ch = 0; ch < SL / KC; ch++) {
        int k0 = ch * KC;
        __syncthreads();
#pragma unroll
        for (int i = 0; i < 16; i++) {
            int idx = t + i * 256;
            int e = idx >> 6, f4 = idx & 63;
            float4 v = *((const float4*)(gwT + (size_t)e * SL + k0) + f4);
            *((float4*)&s.w[e][0] + f4) = v;
        }
        __syncthreads();

        ulonglong2 cv2 = *((const ulonglong2*)&g_c[b][k0 + kk]);
        unsigned long long acc2[4][2];
#pragma unroll
        for (int i = 0; i < 4; i++) { acc2[i][0] = cv2.x; acc2[i][1] = cv2.y; }

#pragma unroll
        for (int e4 = 0; e4 < 16; e4++) {
            const int e = e4 * 4;
            ulonglong2 b0 = *(const ulonglong2*)&s.w[e + 0][kk];
            ulonglong2 b1 = *(const ulonglong2*)&s.w[e + 1][kk];
            ulonglong2 b2 = *(const ulonglong2*)&s.w[e + 2][kk];
            ulonglong2 b3 = *(const ulonglong2*)&s.w[e + 3][kk];
#pragma unroll
            for (int i = 0; i < 4; i++) {
                float4 a = *(const float4*)&s.zq[4 * qg + i][e];
                unsigned long long ax = dup2(a.x), ay = dup2(a.y);
                unsigned long long az = dup2(a.z), aw = dup2(a.w);
                fma2(acc2[i][0], ax, b0.x); fma2(acc2[i][1], ax, b0.y);
                fma2(acc2[i][0], ay, b1.x); fma2(acc2[i][1], ay, b1.y);
                fma2(acc2[i][0], az, b2.x); fma2(acc2[i][1], az, b2.y);
                fma2(acc2[i][0], aw, b3.x); fma2(acc2[i][1], aw, b3.y);
            }
        }
#pragma unroll
        for (int i = 0; i < 4; i++)
            *((ulonglong2*)&s.sc[4 * qg + i][k0 + kk]) =
                make_ulonglong2(acc2[i][0], acc2[i][1]);
    }
    __syncthreads();

    // ---- per-row softmax (warp w owns rows 2w, 2w+1) ----
    int w_id = t >> 5, lane = t & 31;
    const float* zb = z + (size_t)b * SL * ZD;

    for (int rr = 0; rr < 2; rr++) {
        int r = w_id * 2 + rr;
        int msk = mask[b * SL + q0 + r];
        if (lane == 0) { s.mskd[r] = msk; s.cnt[r] = 0; }
        __syncwarp();

        float iz = 0.f;
        if (msk != 0) {
            const float4* row4 = (const float4*)&s.sc[r][0];
            float4* row4w = (float4*)&s.sc[r][0];
            float mx = -3.4e38f;
#pragma unroll
            for (int i = 0; i < 16; i++) {
                float4 v = row4[i * 32 + lane];
                mx = fmaxf(mx, fmaxf(fmaxf(v.x, v.y), fmaxf(v.z, v.w)));
            }
#pragma unroll
            for (int o = 16; o; o >>= 1) mx = fmaxf(mx, __shfl_xor_sync(~0u, mx, o));
            float Zp = 0.f;
            for (int i = 0; i < 16; i++) {
                int idx = i * 32 + lane;
                float4 v = row4[idx];
                float d0 = v.x - mx, d1 = v.y - mx, d2 = v.z - mx, d3 = v.w - mx;
                float dm = fmaxf(fmaxf(d0, d1), fmaxf(d2, d3));
                unsigned bal = __ballot_sync(~0u, dm >= SKIP_T);
                if (bal == 0) { row4w[idx] = make_float4(0.f, 0.f, 0.f, 0.f); continue; }
                float p0 = __expf(d0), p1 = __expf(d1);
                float p2 = __expf(d2), p3 = __expf(d3);
                row4w[idx] = make_float4(p0, p1, p2, p3);
                Zp += (p0 + p1) + (p2 + p3);
                int kb = idx * 4;
                if (p0 > 0.f) { int p = atomicAdd(&s.cnt[r], 1); if (p < CAP) { s.kv[r][p] = kb + 0; s.pv[r][p] = p0; } }
                if (p1 > 0.f) { int p = atomicAdd(&s.cnt[r], 1); if (p < CAP) { s.kv[r][p] = kb + 1; s.pv[r][p] = p1; } }
                if (p2 > 0.f) { int p = atomicAdd(&s.cnt[r], 1); if (p < CAP) { s.kv[r][p] = kb + 2; s.pv[r][p] = p2; } }
                if (p3 > 0.f) { int p = atomicAdd(&s.cnt[r], 1); if (p < CAP) { s.kv[r][p] = kb + 3; s.pv[r][p] = p3; } }
            }
#pragma unroll
            for (int o = 16; o; o >>= 1) Zp += __shfl_xor_sync(~0u, Zp, o);
            iz = 1.0f / Zp;
            if (lane == 0) s.invZ_s[r] = iz;
        }
        __syncwarp();

        float y0 = 0.f, y1 = 0.f;
        if (msk == 0) {
            if (attnp) {
                const float u = 1.0f / 2048.0f;
                float4 u4 = make_float4(u, u, u, u);
                float4* ap = (float4*)(attnp + (size_t)(b * SL + q0 + r) * SL);
#pragma unroll
                for (int i = 0; i < 16; i++) ap[i * 32 + lane] = u4;
            }
            y0 = g_zsum[b][lane] * (1.0f / 2048.0f);
            y1 = g_zsum[b][lane + 32] * (1.0f / 2048.0f);
        } else {
            if (attnp) {
                const float4* row4 = (const float4*)&s.sc[r][0];
                float4* ap = (float4*)(attnp + (size_t)(b * SL + q0 + r) * SL);
#pragma unroll
                for (int i = 0; i < 16; i++) {
                    float4 p = row4[i * 32 + lane];
                    ap[i * 32 + lane] = make_float4(p.x * iz, p.y * iz, p.z * iz, p.w * iz);
                }
            }
            int cnt = s.cnt[r];
            if (cnt <= CAP) {
                for (int i = 0; i < cnt; i++) {
                    float a = s.pv[r][i] * iz;
                    int k = s.kv[r][i];
                    y0 += a * zb[(size_t)k * ZD + lane];
                    y1 += a * zb[(size_t)k * ZD + lane + 32];
                }
            } else {
                for (int k = 0; k < SL; k++) {
                    float p = s.sc[r][k];
                    if (p != 0.f) {
                        float a = p * iz;
                        y0 += a * zb[(size_t)k * ZD + lane];
                        y1 += a * zb[(size_t)k * ZD + lane + 32];
                    }
                }
            }
        }
        s.yT[lane][r] = y0;
        s.yT[lane + 32][r] = y1;
    }
    __syncthreads();

    // ---- output epilogue ----
    if (outp) {
        float acc[QT];
        float ve = g_venc[b][t];
#pragma unroll
        for (int q = 0; q < QT; q++) acc[q] = ve;
#pragma unroll 4
        for (int e = 0; e < ZD; e++) {
            float wvv = wv[(size_t)(HD + e) * HD + t];
            const float4* yr = (const float4*)&s.yT[e][0];
            float4 ya = yr[0], yb = yr[1], yc = yr[2], yd = yr[3];
            acc[0]  += ya.x * wvv; acc[1]  += ya.y * wvv;
            acc[2]  += ya.z * wvv; acc[3]  += ya.w * wvv;
            acc[4]  += yb.x * wvv; acc[5]  += yb.y * wvv;
            acc[6]  += yb.z * wvv; acc[7]  += yb.w * wvv;
            acc[8]  += yc.x * wvv; acc[9]  += yc.y * wvv;
            acc[10] += yc.z * wvv; acc[11] += yc.w * wvv;
            acc[12] += yd.x * wvv; acc[13] += yd.y * wvv;
            acc[14] += yd.z * wvv; acc[15] += yd.w * wvv;
        }
#pragma unroll
        for (int q = 0; q < QT; q++)
            outp[((size_t)b * SL + q0 + q) * HD + t] = acc[q];
    }
}

// ============================== launch =====================================
extern "C" void kernel_launch(void* const* d_in, const int* in_sizes, int n_in,
                              void* d_out, int out_size) {
    const float* ehs  = (const float*)d_in[0];
    // d_in[1] = decoder_hidden_state (unused by reference)
    const float* z    = (const float*)d_in[2];
    const int*   mask = (const int*)d_in[3];
    const float* wq   = (const float*)d_in[4];
    const float* wk   = (const float*)d_in[5];
    const float* wv   = (const float*)d_in[6];

    const long OUT_N = (long)BB * SL * HD;   //  4,194,304
    const long ATT_N = (long)BB * SL * SL;   // 33,554,432
    float* o = (float*)d_out;
    float* outp = nullptr;
    float* attnp = nullptr;
    if ((long)out_size >= OUT_N + ATT_N) { outp = o; attnp = o + OUT_N; }
    else if ((long)out_size == ATT_N)    { attnp = o; }
    else                                 { outp = o; }

    static int attr_set = 0;
    if (!attr_set) {
        cudaFuncSetAttribute(k_attn, cudaFuncAttributeMaxDynamicSharedMemorySize,
                             (int)sizeof(AttnSmem));
        cudaFuncSetAttribute(k_prep2, cudaFuncAttributeMaxDynamicSharedMemorySize,
                             (int)sizeof(P2Smem));
        attr_set = 1;
    }

    k_prep1<<<BB, 256>>>(ehs, z, wq, wv);
    k_prep2<<<4, 256, sizeof(P2Smem)>>>(wq, wk);
    k_wc<<<128, 128>>>(z);
    k_attn<<<BB * (SL / QT), 256, sizeof(AttnSmem)>>>(z, wv, mask, outp, attnp);
}

// round 5
// speedup vs baseline: 1.5339x; 1.2641x over previous
#include <cuda_runtime.h>
#include <math.h>
#include <stdint.h>
#include <stddef.h>

// ---- problem constants ----
#define HD  256      // HIDDEN_DIM
#define ZD  64       // Z_DIM
#define BB  8        // batch
#define SL  2048     // SRC_LEN
#define QT  16       // queries per block in k_attn
#define KC  256      // key chunk in k_attn
#define EH  32       // e-half rows per pipeline stage
#define NST 16       // pipeline stages = (SL/KC) * 2
#define CAP 128      // per-row nonzero-attn list capacity
#define SKIP_T (-88.0f)
#define KZP 260      // padded smem row (floats) for prep2

typedef unsigned long long ull;

// ---- device scratch (no allocation allowed) ----
__device__ float g_venc[BB][HD];
__device__ float g_qenc[BB][HD];
__device__ float g_u[BB][ZD];
__device__ float g_zsum[BB][ZD];
__device__ float g_M[ZD][ZD];
__device__ float g_wT[BB * ZD * SL]; // [b][d][key], w = (M z_k)/16
__device__ float g_c[BB][SL];        // c_k = (u_b . z_k)/16

// ---- packed fp32x2 helpers ----
__device__ __forceinline__ void fma2(ull& d, ull a, ull b) {
    asm("fma.rn.f32x2 %0, %1, %2, %0;" : "+l"(d) : "l"(a), "l"(b));
}
__device__ __forceinline__ ull dup2(float x) {
    ull r;
    asm("mov.b64 %0, {%1, %1};" : "=l"(r) : "f"(x));
    return r;
}
__device__ __forceinline__ void unpack2(float& lo, float& hi, ull v) {
    asm("mov.b64 {%0, %1}, %2;" : "=f"(lo), "=f"(hi) : "l"(v));
}

// ---- cp.async helpers ----
__device__ __forceinline__ void cp16(uint32_t saddr, const void* gaddr) {
    asm volatile("cp.async.cg.shared.global [%0], [%1], 16;"
                 :: "r"(saddr), "l"(gaddr));
}
__device__ __forceinline__ void cp_commit() {
    asm volatile("cp.async.commit_group;");
}
__device__ __forceinline__ void cp_wait0() {
    asm volatile("cp.async.wait_group 0;");
}

// ============ kernel 1a: per-batch enc sums, qenc/venc, zsum ===============
__global__ void k_prep1(const float* __restrict__ ehs,
                        const float* __restrict__ z,
                        const float* __restrict__ wq,
                        const float* __restrict__ wv) {
    __shared__ float enc[HD];
    __shared__ float zs[4][ZD];
    int t = threadIdx.x;
    int b = blockIdx.x;
    enc[t] = ehs[b * HD + t] + ehs[BB * HD + b * HD + t];
    __syncthreads();
    float aq = 0.f, av = 0.f;
#pragma unroll 8
    for (int d = 0; d < HD; d++) {
        float ev = enc[d];
        aq += ev * wq[d * HD + t];
        av += ev * wv[d * HD + t];
    }
    g_qenc[b][t] = aq;
    g_venc[b][t] = av;
    int e = t & 63, part = t >> 6;
    const float* zp = z + (size_t)b * SL * ZD;
    float s = 0.f;
#pragma unroll 8
    for (int k = part * 512; k < part * 512 + 512; k++)
        s += zp[(size_t)k * ZD + e];
    zs[part][e] = s;
    __syncthreads();
    if (t < ZD) g_zsum[b][t] = zs[0][t] + zs[1][t] + zs[2][t] + zs[3][t];
}

// ============ kernel 1b: M = Wq_z Wk_z^T (smem-staged) + u ================
struct __align__(16) P2Smem {
    float kz[ZD][KZP];
    float qz[16][KZP];
    float qe[BB][HD];
};

__global__ void k_prep2(const float* __restrict__ wq,
                        const float* __restrict__ wk) {
    extern __shared__ char smraw[];
    P2Smem& s = *reinterpret_cast<P2Smem*>(smraw);
    int t = threadIdx.x;
    int i = blockIdx.x;
#pragma unroll
    for (int r = 0; r < ZD; r += 4) {
        int e = r + (t >> 6), f4 = t & 63;
        float4 v = *((const float4*)(wk + (size_t)(HD + e) * HD) + f4);
        *((float4*)&s.kz[e][0] + f4) = v;
    }
#pragma unroll
    for (int r = 0; r < 16; r += 4) {
        int dl = r + (t >> 6), f4 = t & 63;
        float4 v = *((const float4*)(wq + (size_t)(HD + i * 16 + dl) * HD) + f4);
        *((float4*)&s.qz[dl][0] + f4) = v;
    }
    __syncthreads();

    int e = t & 63, jg = t >> 6;
    float a0 = 0.f, a1 = 0.f, a2 = 0.f, a3 = 0.f;
#pragma unroll 8
    for (int h4 = 0; h4 < HD / 4; h4++) {
        float4 kv = *((const float4*)&s.kz[e][0] + h4);
        float4 q0 = *((const float4*)&s.qz[jg * 4 + 0][0] + h4);
        float4 q1 = *((const float4*)&s.qz[jg * 4 + 1][0] + h4);
        float4 q2 = *((const float4*)&s.qz[jg * 4 + 2][0] + h4);
        float4 q3 = *((const float4*)&s.qz[jg * 4 + 3][0] + h4);
        a0 += q0.x * kv.x + q0.y * kv.y + q0.z * kv.z + q0.w * kv.w;
        a1 += q1.x * kv.x + q1.y * kv.y + q1.z * kv.z + q1.w * kv.w;
        a2 += q2.x * kv.x + q2.y * kv.y + q2.z * kv.z + q2.w * kv.w;
        a3 += q3.x * kv.x + q3.y * kv.y + q3.z * kv.z + q3.w * kv.w;
    }
    g_M[i * 16 + jg * 4 + 0][e] = a0;
    g_M[i * 16 + jg * 4 + 1][e] = a1;
    g_M[i * 16 + jg * 4 + 2][e] = a2;
    g_M[i * 16 + jg * 4 + 3][e] = a3;

    if (i == 0) {
        for (int idx = t; idx < BB * HD; idx += 256)
            ((float*)s.qe)[idx] = ((const float*)g_qenc)[idx];
        __syncthreads();
#pragma unroll
        for (int bb2 = 0; bb2 < 2; bb2++) {
            int b = (t >> 6) + bb2 * 4;
            float au = 0.f;
#pragma unroll 8
            for (int h4 = 0; h4 < HD / 4; h4++) {
                float4 kv = *((const float4*)&s.kz[e][0] + h4);
                float4 qv = *((const float4*)&s.qe[b][0] + h4);
                au += qv.x * kv.x + qv.y * kv.y + qv.z * kv.z + qv.w * kv.w;
            }
            g_u[b][e] = au;
        }
    }
}

// ===== kernel 2: wT[b,d,k] = (M z_k)[d]/16, c[b,k] = (u_b.z_k)/16 ==========
__global__ void k_wc(const float* __restrict__ z) {
    __shared__ float Ms[ZD][ZD];
    __shared__ float us[ZD];
    int t = threadIdx.x;
    int b = blockIdx.x >> 4;
    int k0 = (blockIdx.x & 15) * 128;
    for (int i = t; i < ZD * ZD / 4; i += 128)
        ((float4*)Ms)[i] = ((const float4*)g_M)[i];
    if (t < ZD) us[t] = g_u[b][t];
    __syncthreads();

    int key = k0 + t;
    const float4* zp4 = (const float4*)(z + ((size_t)b * SL + key) * ZD);
    float zr[ZD];
#pragma unroll
    for (int i = 0; i < ZD / 4; i++) {
        float4 v = zp4[i];
        zr[4 * i + 0] = v.x; zr[4 * i + 1] = v.y;
        zr[4 * i + 2] = v.z; zr[4 * i + 3] = v.w;
    }
    const float inv_t = 0.0625f;
    float cacc = 0.f;
#pragma unroll
    for (int e = 0; e < ZD; e++) cacc += zr[e] * us[e];
    g_c[b][key] = cacc * inv_t;

    float* wt = g_wT + (size_t)b * ZD * SL;
#pragma unroll
    for (int d4 = 0; d4 < ZD / 4; d4++) {
        float a0 = 0.f, a1 = 0.f, a2 = 0.f, a3 = 0.f;
#pragma unroll
        for (int e4 = 0; e4 < ZD / 4; e4++) {
            float4 m0 = ((const float4*)&Ms[4 * d4 + 0][0])[e4];
            float4 m1 = ((const float4*)&Ms[4 * d4 + 1][0])[e4];
            float4 m2 = ((const float4*)&Ms[4 * d4 + 2][0])[e4];
            float4 m3 = ((const float4*)&Ms[4 * d4 + 3][0])[e4];
            float z0 = zr[4 * e4 + 0], z1 = zr[4 * e4 + 1];
            float z2 = zr[4 * e4 + 2], z3 = zr[4 * e4 + 3];
            a0 += m0.x * z0 + m0.y * z1 + m0.z * z2 + m0.w * z3;
            a1 += m1.x * z0 + m1.y * z1 + m1.z * z2 + m1.w * z3;
            a2 += m2.x * z0 + m2.y * z1 + m2.z * z2 + m2.w * z3;
            a3 += m3.x * z0 + m3.y * z1 + m3.z * z2 + m3.w * z3;
        }
        wt[(size_t)(4 * d4 + 0) * SL + key] = a0 * inv_t;
        wt[(size_t)(4 * d4 + 1) * SL + key] = a1 * inv_t;
        wt[(size_t)(4 * d4 + 2) * SL + key] = a2 * inv_t;
        wt[(size_t)(4 * d4 + 3) * SL + key] = a3 * inv_t;
    }
}

// =================== kernel 3: scores + softmax + output ===================
struct __align__(16) AttnSmem {
    float  sc[QT][SL];        // 131072 B: scores -> exp values
    float  w[2][EH][KC];      //  65536 B: double-buffered w e-half chunks
    float2 zq2[QT][ZD];       //   8192 B: duplicated z_q pairs
    float  yT[ZD][QT];        //   4096 B
    float  pv[QT][CAP];       //   8192 B
    int    kv[QT][CAP];       //   8192 B
    int    cnt[QT];
    float  invZ_s[QT];
    int    mskd[QT];
};                             // ~225,472 B

__global__ void __launch_bounds__(256, 1)
k_attn(const float* __restrict__ z, const float* __restrict__ wv,
       const int* __restrict__ mask, float* __restrict__ outp,
       float* __restrict__ attnp) {
    extern __shared__ char smraw[];
    AttnSmem& s = *reinterpret_cast<AttnSmem*>(smraw);
    int t = threadIdx.x;
    int b = blockIdx.x >> 7;
    int q0 = (blockIdx.x & 127) * QT;

    const float* gwT = g_wT + (size_t)b * ZD * SL;

    // fill duplicated zq pairs [QT][ZD]
#pragma unroll
    for (int i = 0; i < 4; i++) {
        int idx = t + i * 256;
        int q = idx >> 6, e = idx & 63;
        float v = z[((size_t)b * SL + q0 + q) * ZD + e];
        s.zq2[q][e] = make_float2(v, v);
    }

    // prefetch stage 0 (chunk 0, e-half 0)
#pragma unroll
    for (int i = 0; i < 8; i++) {
        int idx = t + i * 256;
        int el = idx >> 6, f4 = idx & 63;
        uint32_t sa = (uint32_t)__cvta_generic_to_shared(&s.w[0][el][f4 * 4]);
        cp16(sa, gwT + (size_t)el * SL + f4 * 4);
    }
    cp_commit();

    int kq = t & 63, qg = t >> 6;
    int kk = kq * 4;

    ull acc2[4][2];

    // ---- pipelined score GEMM over 16 stages (8 chunks x 2 e-halves) ----
#pragma unroll 2
    for (int st = 0; st < NST; st++) {
        cp_wait0();
        __syncthreads();          // stage buffer ready; prior reads done

        int nst = st + 1;
        if (nst < NST) {
            int nch = nst >> 1, neh = nst & 1;
#pragma unroll
            for (int i = 0; i < 8; i++) {
                int idx = t + i * 256;
                int el = idx >> 6, f4 = idx & 63;
                uint32_t sa = (uint32_t)__cvta_generic_to_shared(
                    &s.w[nst & 1][el][f4 * 4]);
                cp16(sa, gwT + (size_t)(neh * EH + el) * SL + nch * KC + f4 * 4);
            }
            cp_commit();
        }

        int ch = st >> 1, eh = st & 1, k0 = ch * KC;
        int buf = st & 1;
        if (eh == 0) {
            ulonglong2 cv2 = *((const ulonglong2*)&g_c[b][k0 + kk]);
#pragma unroll
            for (int i = 0; i < 4; i++) { acc2[i][0] = cv2.x; acc2[i][1] = cv2.y; }
        }
        int eb = eh * EH;
#pragma unroll
        for (int e4 = 0; e4 < EH / 4; e4++) {
            const int el = e4 * 4;
            ulonglong2 b0 = *(const ulonglong2*)&s.w[buf][el + 0][kk];
            ulonglong2 b1 = *(const ulonglong2*)&s.w[buf][el + 1][kk];
            ulonglong2 b2 = *(const ulonglong2*)&s.w[buf][el + 2][kk];
            ulonglong2 b3 = *(const ulonglong2*)&s.w[buf][el + 3][kk];
#pragma unroll
            for (int i = 0; i < 4; i++) {
                const float2* zp = &s.zq2[4 * qg + i][eb + el];
                ull a0 = *(const ull*)(zp + 0);
                ull a1 = *(const ull*)(zp + 1);
                ull a2 = *(const ull*)(zp + 2);
                ull a3 = *(const ull*)(zp + 3);
                fma2(acc2[i][0], a0, b0.x); fma2(acc2[i][1], a0, b0.y);
                fma2(acc2[i][0], a1, b1.x); fma2(acc2[i][1], a1, b1.y);
                fma2(acc2[i][0], a2, b2.x); fma2(acc2[i][1], a2, b2.y);
                fma2(acc2[i][0], a3, b3.x); fma2(acc2[i][1], a3, b3.y);
            }
        }
        if (eh == 1) {
#pragma unroll
            for (int i = 0; i < 4; i++)
                *((ulonglong2*)&s.sc[4 * qg + i][k0 + kk]) =
                    make_ulonglong2(acc2[i][0], acc2[i][1]);
        }
    }
    __syncthreads();

    // ---- per-row softmax (warp w owns rows 2w, 2w+1) ----
    int w_id = t >> 5, lane = t & 31;
    const float* zb = z + (size_t)b * SL * ZD;

    for (int rr = 0; rr < 2; rr++) {
        int r = w_id * 2 + rr;
        int msk = mask[b * SL + q0 + r];
        if (lane == 0) { s.mskd[r] = msk; s.cnt[r] = 0; }
        __syncwarp();

        float iz = 0.f;
        if (msk != 0) {
            const float4* row4 = (const float4*)&s.sc[r][0];
            float4* row4w = (float4*)&s.sc[r][0];
            float mx = -3.4e38f;
#pragma unroll
            for (int i = 0; i < 16; i++) {
                float4 v = row4[i * 32 + lane];
                mx = fmaxf(mx, fmaxf(fmaxf(v.x, v.y), fmaxf(v.z, v.w)));
            }
#pragma unroll
            for (int o = 16; o; o >>= 1) mx = fmaxf(mx, __shfl_xor_sync(~0u, mx, o));
            float Zp = 0.f;
            for (int i = 0; i < 16; i++) {
                int idx = i * 32 + lane;
                float4 v = row4[idx];
                float d0 = v.x - mx, d1 = v.y - mx, d2 = v.z - mx, d3 = v.w - mx;
                float dm = fmaxf(fmaxf(d0, d1), fmaxf(d2, d3));
                unsigned bal = __ballot_sync(~0u, dm >= SKIP_T);
                if (bal == 0) { row4w[idx] = make_float4(0.f, 0.f, 0.f, 0.f); continue; }
                float p0 = __expf(d0), p1 = __expf(d1);
                float p2 = __expf(d2), p3 = __expf(d3);
                row4w[idx] = make_float4(p0, p1, p2, p3);
                Zp += (p0 + p1) + (p2 + p3);
                int kb = idx * 4;
                if (p0 > 0.f) { int p = atomicAdd(&s.cnt[r], 1); if (p < CAP) { s.kv[r][p] = kb + 0; s.pv[r][p] = p0; } }
                if (p1 > 0.f) { int p = atomicAdd(&s.cnt[r], 1); if (p < CAP) { s.kv[r][p] = kb + 1; s.pv[r][p] = p1; } }
                if (p2 > 0.f) { int p = atomicAdd(&s.cnt[r], 1); if (p < CAP) { s.kv[r][p] = kb + 2; s.pv[r][p] = p2; } }
                if (p3 > 0.f) { int p = atomicAdd(&s.cnt[r], 1); if (p < CAP) { s.kv[r][p] = kb + 3; s.pv[r][p] = p3; } }
            }
#pragma unroll
            for (int o = 16; o; o >>= 1) Zp += __shfl_xor_sync(~0u, Zp, o);
            iz = 1.0f / Zp;
            if (lane == 0) s.invZ_s[r] = iz;
        }
        __syncwarp();

        float y0 = 0.f, y1 = 0.f;
        if (msk == 0) {
            if (attnp) {
                const float u = 1.0f / 2048.0f;
                float4 u4 = make_float4(u, u, u, u);
                float4* ap = (float4*)(attnp + (size_t)(b * SL + q0 + r) * SL);
#pragma unroll
                for (int i = 0; i < 16; i++) __stcs(&ap[i * 32 + lane], u4);
            }
            y0 = g_zsum[b][lane] * (1.0f / 2048.0f);
            y1 = g_zsum[b][lane + 32] * (1.0f / 2048.0f);
        } else {
            if (attnp) {
                const float4* row4 = (const float4*)&s.sc[r][0];
                float4* ap = (float4*)(attnp + (size_t)(b * SL + q0 + r) * SL);
#pragma unroll
                for (int i = 0; i < 16; i++) {
                    float4 p = row4[i * 32 + lane];
                    __stcs(&ap[i * 32 + lane],
                           make_float4(p.x * iz, p.y * iz, p.z * iz, p.w * iz));
                }
            }
            int cnt = s.cnt[r];
            if (cnt <= CAP) {
                for (int i = 0; i < cnt; i++) {
                    float a = s.pv[r][i] * iz;
                    int k = s.kv[r][i];
                    y0 += a * zb[(size_t)k * ZD + lane];
                    y1 += a * zb[(size_t)k * ZD + lane + 32];
                }
            } else {
                for (int k = 0; k < SL; k++) {
                    float p = s.sc[r][k];
                    if (p != 0.f) {
                        float a = p * iz;
                        y0 += a * zb[(size_t)k * ZD + lane];
                        y1 += a * zb[(size_t)k * ZD + lane + 32];
                    }
                }
            }
        }
        s.yT[lane][r] = y0;
        s.yT[lane + 32][r] = y1;
    }
    __syncthreads();

    // ---- output epilogue: packed f32x2 over q-pairs ----
    if (outp) {
        float ve = g_venc[b][t];
        ull ved = dup2(ve);
        ull acc[8];
#pragma unroll
        for (int j = 0; j < 8; j++) acc[j] = ved;
#pragma unroll 4
        for (int e = 0; e < ZD; e++) {
            float wvv = wv[(size_t)(HD + e) * HD + t];
            ull wd = dup2(wvv);
            const ulonglong2* yr = (const ulonglong2*)&s.yT[e][0];
            ulonglong2 ya = yr[0], yb2 = yr[1], yc = yr[2], yd = yr[3];
            fma2(acc[0], wd, ya.x);  fma2(acc[1], wd, ya.y);
            fma2(acc[2], wd, yb2.x); fma2(acc[3], wd, yb2.y);
            fma2(acc[4], wd, yc.x);  fma2(acc[5], wd, yc.y);
            fma2(acc[6], wd, yd.x);  fma2(acc[7], wd, yd.y);
        }
#pragma unroll
        for (int j = 0; j < 8; j++) {
            float lo, hi;
            unpack2(lo, hi, acc[j]);
            outp[((size_t)b * SL + q0 + 2 * j + 0) * HD + t] = lo;
            outp[((size_t)b * SL + q0 + 2 * j + 1) * HD + t] = hi;
        }
    }
}

// ============================== launch =====================================
extern "C" void kernel_launch(void* const* d_in, const int* in_sizes, int n_in,
                              void* d_out, int out_size) {
    const float* ehs  = (const float*)d_in[0];
    // d_in[1] = decoder_hidden_state (unused by reference)
    const float* z    = (const float*)d_in[2];
    const int*   mask = (const int*)d_in[3];
    const float* wq   = (const float*)d_in[4];
    const float* wk   = (const float*)d_in[5];
    const float* wv   = (const float*)d_in[6];

    const long OUT_N = (long)BB * SL * HD;   //  4,194,304
    const long ATT_N = (long)BB * SL * SL;   // 33,554,432
    float* o = (float*)d_out;
    float* outp = nullptr;
    float* attnp = nullptr;
    if ((long)out_size >= OUT_N + ATT_N) { outp = o; attnp = o + OUT_N; }
    else if ((long)out_size == ATT_N)    { attnp = o; }
    else                                 { outp = o; }

    static int attr_set = 0;
    if (!attr_set) {
        cudaFuncSetAttribute(k_attn, cudaFuncAttributeMaxDynamicSharedMemorySize,
                             (int)sizeof(AttnSmem));
        cudaFuncSetAttribute(k_prep2, cudaFuncAttributeMaxDynamicSharedMemorySize,
                             (int)sizeof(P2Smem));
        attr_set = 1;
    }

    k_prep1<<<BB, 256>>>(ehs, z, wq, wv);
    k_prep2<<<4, 256, sizeof(P2Smem)>>>(wq, wk);
    k_wc<<<128, 128>>>(z);
    k_attn<<<BB * (SL / QT), 256, sizeof(AttnSmem)>>>(z, wv, mask, outp, attnp);
}

// round 6
// speedup vs baseline: 1.6792x; 1.0947x over previous
#include <cuda_runtime.h>
#include <math.h>
#include <stdint.h>
#include <stddef.h>

// ---- problem constants ----
#define HD  256      // HIDDEN_DIM
#define ZD  64       // Z_DIM
#define BB  8        // batch
#define SL  2048     // SRC_LEN
#define QT  16       // queries per block in k_attn
#define KC  1024     // key chunk in k_attn
#define ES  8        // e-rows per pipeline stage
#define NST 16       // stages = (SL/KC) * (ZD/ES)
#define CAP 128      // per-row nonzero-attn list capacity
#define SKIP_T (-88.0f)
#define KZP 260      // padded smem row (floats) for prep2

typedef unsigned long long ull;

// ---- device scratch (no allocation allowed) ----
__device__ float g_venc[BB][HD];
__device__ float g_qenc[BB][HD];
__device__ float g_u[BB][ZD];
__device__ float g_zsum[BB][ZD];
__device__ float g_M[ZD][ZD];
__device__ float g_wT[BB * ZD * SL]; // [b][d][key], w = (M z_k)/16
__device__ float g_c[BB][SL];        // c_k = (u_b . z_k)/16

// ---- packed fp32x2 helpers ----
__device__ __forceinline__ void fma2(ull& d, ull a, ull b) {
    asm("fma.rn.f32x2 %0, %1, %2, %0;" : "+l"(d) : "l"(a), "l"(b));
}
__device__ __forceinline__ ull dup2(float x) {
    ull r;
    asm("mov.b64 %0, {%1, %1};" : "=l"(r) : "f"(x));
    return r;
}
__device__ __forceinline__ void unpack2(float& lo, float& hi, ull v) {
    asm("mov.b64 {%0, %1}, %2;" : "=f"(lo), "=f"(hi) : "l"(v));
}

// ---- cp.async helpers ----
__device__ __forceinline__ void cp16(uint32_t saddr, const void* gaddr) {
    asm volatile("cp.async.cg.shared.global [%0], [%1], 16;"
                 :: "r"(saddr), "l"(gaddr));
}
__device__ __forceinline__ void cp_commit() {
    asm volatile("cp.async.commit_group;");
}
__device__ __forceinline__ void cp_wait0() {
    asm volatile("cp.async.wait_group 0;");
}

// ============ kernel 1a: per-batch enc sums, qenc/venc, zsum ===============
__global__ void k_prep1(const float* __restrict__ ehs,
                        const float* __restrict__ z,
                        const float* __restrict__ wq,
                        const float* __restrict__ wv) {
    __shared__ float enc[HD];
    __shared__ float zs[4][ZD];
    int t = threadIdx.x;
    int b = blockIdx.x;
    enc[t] = ehs[b * HD + t] + ehs[BB * HD + b * HD + t];
    __syncthreads();
    float aq = 0.f, av = 0.f;
#pragma unroll 8
    for (int d = 0; d < HD; d++) {
        float ev = enc[d];
        aq += ev * wq[d * HD + t];
        av += ev * wv[d * HD + t];
    }
    g_qenc[b][t] = aq;
    g_venc[b][t] = av;
    int e = t & 63, part = t >> 6;
    const float* zp = z + (size_t)b * SL * ZD;
    float s = 0.f;
#pragma unroll 8
    for (int k = part * 512; k < part * 512 + 512; k++)
        s += zp[(size_t)k * ZD + e];
    zs[part][e] = s;
    __syncthreads();
    if (t < ZD) g_zsum[b][t] = zs[0][t] + zs[1][t] + zs[2][t] + zs[3][t];
}

// ============ kernel 1b: M = Wq_z Wk_z^T (smem-staged) + u ================
struct __align__(16) P2Smem {
    float kz[ZD][KZP];
    float qz[16][KZP];
    float qe[BB][HD];
};

__global__ void k_prep2(const float* __restrict__ wq,
                        const float* __restrict__ wk) {
    extern __shared__ char smraw[];
    P2Smem& s = *reinterpret_cast<P2Smem*>(smraw);
    int t = threadIdx.x;
    int i = blockIdx.x;
#pragma unroll
    for (int r = 0; r < ZD; r += 4) {
        int e = r + (t >> 6), f4 = t & 63;
        float4 v = *((const float4*)(wk + (size_t)(HD + e) * HD) + f4);
        *((float4*)&s.kz[e][0] + f4) = v;
    }
#pragma unroll
    for (int r = 0; r < 16; r += 4) {
        int dl = r + (t >> 6), f4 = t & 63;
        float4 v = *((const float4*)(wq + (size_t)(HD + i * 16 + dl) * HD) + f4);
        *((float4*)&s.qz[dl][0] + f4) = v;
    }
    __syncthreads();

    int e = t & 63, jg = t >> 6;
    float a0 = 0.f, a1 = 0.f, a2 = 0.f, a3 = 0.f;
#pragma unroll 8
    for (int h4 = 0; h4 < HD / 4; h4++) {
        float4 kv = *((const float4*)&s.kz[e][0] + h4);
        float4 q0 = *((const float4*)&s.qz[jg * 4 + 0][0] + h4);
        float4 q1 = *((const float4*)&s.qz[jg * 4 + 1][0] + h4);
        float4 q2 = *((const float4*)&s.qz[jg * 4 + 2][0] + h4);
        float4 q3 = *((const float4*)&s.qz[jg * 4 + 3][0] + h4);
        a0 += q0.x * kv.x + q0.y * kv.y + q0.z * kv.z + q0.w * kv.w;
        a1 += q1.x * kv.x + q1.y * kv.y + q1.z * kv.z + q1.w * kv.w;
        a2 += q2.x * kv.x + q2.y * kv.y + q2.z * kv.z + q2.w * kv.w;
        a3 += q3.x * kv.x + q3.y * kv.y + q3.z * kv.z + q3.w * kv.w;
    }
    g_M[i * 16 + jg * 4 + 0][e] = a0;
    g_M[i * 16 + jg * 4 + 1][e] = a1;
    g_M[i * 16 + jg * 4 + 2][e] = a2;
    g_M[i * 16 + jg * 4 + 3][e] = a3;

    if (i == 0) {
        for (int idx = t; idx < BB * HD; idx += 256)
            ((float*)s.qe)[idx] = ((const float*)g_qenc)[idx];
        __syncthreads();
#pragma unroll
        for (int bb2 = 0; bb2 < 2; bb2++) {
            int b = (t >> 6) + bb2 * 4;
            float au = 0.f;
#pragma unroll 8
            for (int h4 = 0; h4 < HD / 4; h4++) {
                float4 kv = *((const float4*)&s.kz[e][0] + h4);
                float4 qv = *((const float4*)&s.qe[b][0] + h4);
                au += qv.x * kv.x + qv.y * kv.y + qv.z * kv.z + qv.w * kv.w;
            }
            g_u[b][e] = au;
        }
    }
}

// ===== kernel 2: wT[b,d,k] = (M z_k)[d]/16, c[b,k] = (u_b.z_k)/16 ==========
__global__ void k_wc(const float* __restrict__ z) {
    __shared__ float Ms[ZD][ZD];
    __shared__ float us[ZD];
    int t = threadIdx.x;
    int b = blockIdx.x >> 4;
    int k0 = (blockIdx.x & 15) * 128;
    for (int i = t; i < ZD * ZD / 4; i += 128)
        ((float4*)Ms)[i] = ((const float4*)g_M)[i];
    if (t < ZD) us[t] = g_u[b][t];
    __syncthreads();

    int key = k0 + t;
    const float4* zp4 = (const float4*)(z + ((size_t)b * SL + key) * ZD);
    float zr[ZD];
#pragma unroll
    for (int i = 0; i < ZD / 4; i++) {
        float4 v = zp4[i];
        zr[4 * i + 0] = v.x; zr[4 * i + 1] = v.y;
        zr[4 * i + 2] = v.z; zr[4 * i + 3] = v.w;
    }
    const float inv_t = 0.0625f;
    float cacc = 0.f;
#pragma unroll
    for (int e = 0; e < ZD; e++) cacc += zr[e] * us[e];
    g_c[b][key] = cacc * inv_t;

    float* wt = g_wT + (size_t)b * ZD * SL;
#pragma unroll
    for (int d4 = 0; d4 < ZD / 4; d4++) {
        float a0 = 0.f, a1 = 0.f, a2 = 0.f, a3 = 0.f;
#pragma unroll
        for (int e4 = 0; e4 < ZD / 4; e4++) {
            float4 m0 = ((const float4*)&Ms[4 * d4 + 0][0])[e4];
            float4 m1 = ((const float4*)&Ms[4 * d4 + 1][0])[e4];
            float4 m2 = ((const float4*)&Ms[4 * d4 + 2][0])[e4];
            float4 m3 = ((const float4*)&Ms[4 * d4 + 3][0])[e4];
            float z0 = zr[4 * e4 + 0], z1 = zr[4 * e4 + 1];
            float z2 = zr[4 * e4 + 2], z3 = zr[4 * e4 + 3];
            a0 += m0.x * z0 + m0.y * z1 + m0.z * z2 + m0.w * z3;
            a1 += m1.x * z0 + m1.y * z1 + m1.z * z2 + m1.w * z3;
            a2 += m2.x * z0 + m2.y * z1 + m2.z * z2 + m2.w * z3;
            a3 += m3.x * z0 + m3.y * z1 + m3.z * z2 + m3.w * z3;
        }
        wt[(size_t)(4 * d4 + 0) * SL + key] = a0 * inv_t;
        wt[(size_t)(4 * d4 + 1) * SL + key] = a1 * inv_t;
        wt[(size_t)(4 * d4 + 2) * SL + key] = a2 * inv_t;
        wt[(size_t)(4 * d4 + 3) * SL + key] = a3 * inv_t;
    }
}

// =================== kernel 3: scores + softmax + output ===================
// 512 threads, 8q x 4k micro-tile, KC=1024-key chunks, 8-e-row stages
struct __align__(16) AttnSmem {
    float  sc[QT][SL];        // 131072 B: scores -> exp values
    float  w[2][ES][KC];      //  65536 B: double-buffered w stage (8 e-rows x 1024 keys)
    float2 zq2[QT][ZD];       //   8192 B: duplicated z_q pairs
    float  yT[ZD][QT];        //   4096 B
    float  pv[QT][CAP];       //   8192 B
    int    kv[QT][CAP];       //   8192 B
    int    cnt[QT];
    float  invZ_s[QT];
    int    mskd[QT];
};                             // ~225,472 B

__global__ void __launch_bounds__(512, 1)
k_attn(const float* __restrict__ z, const float* __restrict__ wv,
       const int* __restrict__ mask, float* __restrict__ outp,
       float* __restrict__ attnp) {
    extern __shared__ char smraw[];
    AttnSmem& s = *reinterpret_cast<AttnSmem*>(smraw);
    int t = threadIdx.x;
    int b = blockIdx.x >> 7;
    int q0 = (blockIdx.x & 127) * QT;

    const float* gwT = g_wT + (size_t)b * ZD * SL;

    // fill duplicated zq pairs [QT][ZD]
#pragma unroll
    for (int i = 0; i < 2; i++) {
        int idx = t + i * 512;
        int q = idx >> 6, e = idx & 63;
        float v = z[((size_t)b * SL + q0 + q) * ZD + e];
        s.zq2[q][e] = make_float2(v, v);
    }

    // prefetch stage 0 (chunk 0, e-slice 0): 8 rows x 1024 keys
#pragma unroll
    for (int i = 0; i < 4; i++) {
        int idx = t + i * 512;
        int el = idx >> 8, f4 = idx & 255;   // 256 float4 per row
        uint32_t sa = (uint32_t)__cvta_generic_to_shared(&s.w[0][el][f4 * 4]);
        cp16(sa, gwT + (size_t)el * SL + f4 * 4);
    }
    cp_commit();

    int kq = t & 255, qg = t >> 8;   // 2 q-groups of 8 rows; 256 k-threads x 4 keys
    int kk = kq * 4;

    ull acc2[8][2];

    // ---- pipelined score GEMM over 16 stages (2 chunks x 8 e-slices) ----
    for (int st = 0; st < NST; st++) {
        cp_wait0();
        __syncthreads();          // stage buffer ready; prior reads done

        int nst = st + 1;
        if (nst < NST) {
            int nch = nst >> 3, nes = nst & 7;
#pragma unroll
            for (int i = 0; i < 4; i++) {
                int idx = t + i * 512;
                int el = idx >> 8, f4 = idx & 255;
                uint32_t sa = (uint32_t)__cvta_generic_to_shared(
                    &s.w[nst & 1][el][f4 * 4]);
                cp16(sa, gwT + (size_t)(nes * ES + el) * SL + nch * KC + f4 * 4);
            }
            cp_commit();
        }

        int ch = st >> 3, es = st & 7, buf = st & 1;
        int k0 = ch * KC;
        if (es == 0) {
            ulonglong2 cv2 = *((const ulonglong2*)&g_c[b][k0 + kk]);
#pragma unroll
            for (int i = 0; i < 8; i++) { acc2[i][0] = cv2.x; acc2[i][1] = cv2.y; }
        }
        int eb = es * ES;
#pragma unroll
        for (int e4 = 0; e4 < 2; e4++) {
            const int el = e4 * 4;
            ulonglong2 b0 = *(const ulonglong2*)&s.w[buf][el + 0][kk];
            ulonglong2 b1 = *(const ulonglong2*)&s.w[buf][el + 1][kk];
            ulonglong2 b2 = *(const ulonglong2*)&s.w[buf][el + 2][kk];
            ulonglong2 b3 = *(const ulonglong2*)&s.w[buf][el + 3][kk];
#pragma unroll
            for (int i = 0; i < 8; i++) {
                const ulonglong2* ap =
                    (const ulonglong2*)&s.zq2[8 * qg + i][eb + el];
                ulonglong2 aA = ap[0], aB = ap[1];
                fma2(acc2[i][0], aA.x, b0.x); fma2(acc2[i][1], aA.x, b0.y);
                fma2(acc2[i][0], aA.y, b1.x); fma2(acc2[i][1], aA.y, b1.y);
                fma2(acc2[i][0], aB.x, b2.x); fma2(acc2[i][1], aB.x, b2.y);
                fma2(acc2[i][0], aB.y, b3.x); fma2(acc2[i][1], aB.y, b3.y);
            }
        }
        if (es == 7) {
#pragma unroll
            for (int i = 0; i < 8; i++)
                *((ulonglong2*)&s.sc[8 * qg + i][k0 + kk]) =
                    make_ulonglong2(acc2[i][0], acc2[i][1]);
        }
    }
    __syncthreads();

    // ---- per-row softmax: 16 warps, one row each ----
    int w_id = t >> 5, lane = t & 31;
    const float* zb = z + (size_t)b * SL * ZD;
    {
        int r = w_id;
        int msk = mask[b * SL + q0 + r];
        if (lane == 0) { s.mskd[r] = msk; s.cnt[r] = 0; }
        __syncwarp();

        float iz = 0.f;
        if (msk != 0) {
            const float4* row4 = (const float4*)&s.sc[r][0];
            float4* row4w = (float4*)&s.sc[r][0];
            float mx = -3.4e38f;
#pragma unroll
            for (int i = 0; i < 16; i++) {
                float4 v = row4[i * 32 + lane];
                mx = fmaxf(mx, fmaxf(fmaxf(v.x, v.y), fmaxf(v.z, v.w)));
            }
#pragma unroll
            for (int o = 16; o; o >>= 1) mx = fmaxf(mx, __shfl_xor_sync(~0u, mx, o));
            float Zp = 0.f;
            for (int i = 0; i < 16; i++) {
                int idx = i * 32 + lane;
                float4 v = row4[idx];
                float d0 = v.x - mx, d1 = v.y - mx, d2 = v.z - mx, d3 = v.w - mx;
                float dm = fmaxf(fmaxf(d0, d1), fmaxf(d2, d3));
                unsigned bal = __ballot_sync(~0u, dm >= SKIP_T);
                if (bal == 0) { row4w[idx] = make_float4(0.f, 0.f, 0.f, 0.f); continue; }
                float p0 = __expf(d0), p1 = __expf(d1);
                float p2 = __expf(d2), p3 = __expf(d3);
                row4w[idx] = make_float4(p0, p1, p2, p3);
                Zp += (p0 + p1) + (p2 + p3);
                int kb = idx * 4;
                if (p0 > 0.f) { int p = atomicAdd(&s.cnt[r], 1); if (p < CAP) { s.kv[r][p] = kb + 0; s.pv[r][p] = p0; } }
                if (p1 > 0.f) { int p = atomicAdd(&s.cnt[r], 1); if (p < CAP) { s.kv[r][p] = kb + 1; s.pv[r][p] = p1; } }
                if (p2 > 0.f) { int p = atomicAdd(&s.cnt[r], 1); if (p < CAP) { s.kv[r][p] = kb + 2; s.pv[r][p] = p2; } }
                if (p3 > 0.f) { int p = atomicAdd(&s.cnt[r], 1); if (p < CAP) { s.kv[r][p] = kb + 3; s.pv[r][p] = p3; } }
            }
#pragma unroll
            for (int o = 16; o; o >>= 1) Zp += __shfl_xor_sync(~0u, Zp, o);
            iz = 1.0f / Zp;
            if (lane == 0) s.invZ_s[r] = iz;
        }
        __syncwarp();

        float y0 = 0.f, y1 = 0.f;
        if (msk == 0) {
            if (attnp) {
                const float u = 1.0f / 2048.0f;
                float4 u4 = make_float4(u, u, u, u);
                float4* ap = (float4*)(attnp + (size_t)(b * SL + q0 + r) * SL);
#pragma unroll
                for (int i = 0; i < 16; i++) __stcs(&ap[i * 32 + lane], u4);
            }
            y0 = g_zsum[b][lane] * (1.0f / 2048.0f);
            y1 = g_zsum[b][lane + 32] * (1.0f / 2048.0f);
        } else {
            if (attnp) {
                const float4* row4 = (const float4*)&s.sc[r][0];
                float4* ap = (float4*)(attnp + (size_t)(b * SL + q0 + r) * SL);
#pragma unroll
                for (int i = 0; i < 16; i++) {
                    float4 p = row4[i * 32 + lane];
                    __stcs(&ap[i * 32 + lane],
                           make_float4(p.x * iz, p.y * iz, p.z * iz, p.w * iz));
                }
            }
            int cnt = s.cnt[r];
            if (cnt <= CAP) {
                for (int i = 0; i < cnt; i++) {
                    float a = s.pv[r][i] * iz;
                    int k = s.kv[r][i];
                    y0 += a * zb[(size_t)k * ZD + lane];
                    y1 += a * zb[(size_t)k * ZD + lane + 32];
                }
            } else {
                for (int k = 0; k < SL; k++) {
                    float p = s.sc[r][k];
                    if (p != 0.f) {
                        float a = p * iz;
                        y0 += a * zb[(size_t)k * ZD + lane];
                        y1 += a * zb[(size_t)k * ZD + lane + 32];
                    }
                }
            }
        }
        s.yT[lane][r] = y0;
        s.yT[lane + 32][r] = y1;
    }
    __syncthreads();

    // ---- output epilogue: packed f32x2 over q-pairs, 512 threads ----
    if (outp) {
        int h = t & 255, qh = t >> 8;    // qh: which 8-q half
        float ve = g_venc[b][h];
        ull ved = dup2(ve);
        ull acc[4];
#pragma unroll
        for (int j = 0; j < 4; j++) acc[j] = ved;
#pragma unroll 4
        for (int e = 0; e < ZD; e++) {
            float wvv = wv[(size_t)(HD + e) * HD + h];
            ull wd = dup2(wvv);
            const ulonglong2* yr = ((const ulonglong2*)&s.yT[e][0]) + qh * 2;
            ulonglong2 ya = yr[0], yb2 = yr[1];
            fma2(acc[0], wd, ya.x);  fma2(acc[1], wd, ya.y);
            fma2(acc[2], wd, yb2.x); fma2(acc[3], wd, yb2.y);
        }
#pragma unroll
        for (int j = 0; j < 4; j++) {
            float lo, hi;
            unpack2(lo, hi, acc[j]);
            outp[((size_t)b * SL + q0 + qh * 8 + 2 * j + 0) * HD + h] = lo;
            outp[((size_t)b * SL + q0 + qh * 8 + 2 * j + 1) * HD + h] = hi;
        }
    }
}

// ============================== launch =====================================
extern "C" void kernel_launch(void* const* d_in, const int* in_sizes, int n_in,
                              void* d_out, int out_size) {
    const float* ehs  = (const float*)d_in[0];
    // d_in[1] = decoder_hidden_state (unused by reference)
    const float* z    = (const float*)d_in[2];
    const int*   mask = (const int*)d_in[3];
    const float* wq   = (const float*)d_in[4];
    const float* wk   = (const float*)d_in[5];
    const float* wv   = (const float*)d_in[6];

    const long OUT_N = (long)BB * SL * HD;   //  4,194,304
    const long ATT_N = (long)BB * SL * SL;   // 33,554,432
    float* o = (float*)d_out;
    float* outp = nullptr;
    float* attnp = nullptr;
    if ((long)out_size >= OUT_N + ATT_N) { outp = o; attnp = o + OUT_N; }
    else if ((long)out_size == ATT_N)    { attnp = o; }
    else                                 { outp = o; }

    static int attr_set = 0;
    if (!attr_set) {
        cudaFuncSetAttribute(k_attn, cudaFuncAttributeMaxDynamicSharedMemorySize,
                             (int)sizeof(AttnSmem));
        cudaFuncSetAttribute(k_prep2, cudaFuncAttributeMaxDynamicSharedMemorySize,
                             (int)sizeof(P2Smem));
        attr_set = 1;
    }

    k_prep1<<<BB, 256>>>(ehs, z, wq, wv);
    k_prep2<<<4, 256, sizeof(P2Smem)>>>(wq, wk);
    k_wc<<<128, 128>>>(z);
    k_attn<<<BB * (SL / QT), 512, sizeof(AttnSmem)>>>(z, wv, mask, outp, attnp);
}

// round 7
// speedup vs baseline: 1.7651x; 1.0512x over previous
#include <cuda_runtime.h>
#include <math.h>
#include <stdint.h>
#include <stddef.h>

// ---- problem constants ----
#define HD  256      // HIDDEN_DIM
#define ZD  64       // Z_DIM
#define BB  8        // batch
#define SL  2048     // SRC_LEN
#define QT  16       // queries per block in k_attn
#define KC  1024     // key chunk in k_attn
#define ES  8        // e-rows per pipeline stage
#define NST 16       // stages = (SL/KC) * (ZD/ES)
#define CAP 128      // per-row nonzero-attn list capacity
#define SKIP_T (-88.0f)
#define KZP 260      // padded smem row (floats) for prep M-part

typedef unsigned long long ull;

// ---- device scratch (no allocation allowed) ----
__device__ float g_venc[BB][HD];
__device__ float g_qenc[BB][HD];
__device__ float g_zsum[BB][ZD];
__device__ float g_M[ZD][ZD];
__device__ float g_wT[BB * ZD * SL]; // [b][d][key], w = (M z_k)/16
__device__ float g_c[BB][SL];        // c_k = (u_b . z_k)/16

// ---- packed fp32x2 helpers ----
__device__ __forceinline__ void fma2(ull& d, ull a, ull b) {
    asm("fma.rn.f32x2 %0, %1, %2, %0;" : "+l"(d) : "l"(a), "l"(b));
}
__device__ __forceinline__ ull dup2(float x) {
    ull r;
    asm("mov.b64 %0, {%1, %1};" : "=l"(r) : "f"(x));
    return r;
}
__device__ __forceinline__ void unpack2(float& lo, float& hi, ull v) {
    asm("mov.b64 {%0, %1}, %2;" : "=f"(lo), "=f"(hi) : "l"(v));
}

// ---- cp.async helpers ----
__device__ __forceinline__ void cp16(uint32_t saddr, const void* gaddr) {
    asm volatile("cp.async.cg.shared.global [%0], [%1], 16;"
                 :: "r"(saddr), "l"(gaddr));
}
__device__ __forceinline__ void cp_commit() {
    asm volatile("cp.async.commit_group;");
}
__device__ __forceinline__ void cp_wait0() {
    asm volatile("cp.async.wait_group 0;");
}

// ====== kernel 1 (fused): blocks 0..7 per-batch consts; 8..11 M tiles ======
// dynamic smem: max(prep1 small, M part kz+qz = 83200 B)
__global__ void k_prep(const float* __restrict__ ehs,
                       const float* __restrict__ z,
                       const float* __restrict__ wq,
                       const float* __restrict__ wk,
                       const float* __restrict__ wv) {
    extern __shared__ char smraw[];
    int t = threadIdx.x;
    if (blockIdx.x < BB) {
        float* enc = (float*)smraw;          // [HD]
        float* zs  = enc + HD;               // [4][ZD]
        int b = blockIdx.x;
        enc[t] = ehs[b * HD + t] + ehs[BB * HD + b * HD + t];
        __syncthreads();
        float aq = 0.f, av = 0.f;
#pragma unroll 8
        for (int d = 0; d < HD; d++) {
            float ev = enc[d];
            aq += ev * wq[d * HD + t];
            av += ev * wv[d * HD + t];
        }
        g_qenc[b][t] = aq;
        g_venc[b][t] = av;
        int e = t & 63, part = t >> 6;
        const float* zp = z + (size_t)b * SL * ZD;
        float s = 0.f;
#pragma unroll 8
        for (int k = part * 512; k < part * 512 + 512; k++)
            s += zp[(size_t)k * ZD + e];
        zs[part * ZD + e] = s;
        __syncthreads();
        if (t < ZD)
            g_zsum[b][t] = zs[0 * ZD + t] + zs[1 * ZD + t] +
                           zs[2 * ZD + t] + zs[3 * ZD + t];
    } else {
        // M[d][e] = sum_h Wq_z[d,h] * Wk_z[e,h], smem-staged
        float (*kz)[KZP] = (float (*)[KZP])smraw;                  // [ZD][KZP]
        float (*qz)[KZP] = (float (*)[KZP])(smraw + ZD * KZP * 4); // [16][KZP]
        int i = blockIdx.x - BB;
#pragma unroll
        for (int r = 0; r < ZD; r += 4) {
            int e = r + (t >> 6), f4 = t & 63;
            float4 v = *((const float4*)(wk + (size_t)(HD + e) * HD) + f4);
            *((float4*)&kz[e][0] + f4) = v;
        }
#pragma unroll
        for (int r = 0; r < 16; r += 4) {
            int dl = r + (t >> 6), f4 = t & 63;
            float4 v = *((const float4*)(wq + (size_t)(HD + i * 16 + dl) * HD) + f4);
            *((float4*)&qz[dl][0] + f4) = v;
        }
        __syncthreads();
        int e = t & 63, jg = t >> 6;
        float a0 = 0.f, a1 = 0.f, a2 = 0.f, a3 = 0.f;
#pragma unroll 8
        for (int h4 = 0; h4 < HD / 4; h4++) {
            float4 kv = *((const float4*)&kz[e][0] + h4);
            float4 q0 = *((const float4*)&qz[jg * 4 + 0][0] + h4);
            float4 q1 = *((const float4*)&qz[jg * 4 + 1][0] + h4);
            float4 q2 = *((const float4*)&qz[jg * 4 + 2][0] + h4);
            float4 q3 = *((const float4*)&qz[jg * 4 + 3][0] + h4);
            a0 += q0.x * kv.x + q0.y * kv.y + q0.z * kv.z + q0.w * kv.w;
            a1 += q1.x * kv.x + q1.y * kv.y + q1.z * kv.z + q1.w * kv.w;
            a2 += q2.x * kv.x + q2.y * kv.y + q2.z * kv.z + q2.w * kv.w;
            a3 += q3.x * kv.x + q3.y * kv.y + q3.z * kv.z + q3.w * kv.w;
        }
        g_M[i * 16 + jg * 4 + 0][e] = a0;
        g_M[i * 16 + jg * 4 + 1][e] = a1;
        g_M[i * 16 + jg * 4 + 2][e] = a2;
        g_M[i * 16 + jg * 4 + 3][e] = a3;
    }
}

// ===== kernel 2: wT[b,d,k] = (M z_k)[d]/16, c[b,k] = (u_b.z_k)/16 ==========
// grid = 128 blocks * 256 threads; 128 keys/block, d split across 2 halves
__global__ void k_wc(const float* __restrict__ z,
                     const float* __restrict__ wk) {
    __shared__ float Ms[ZD][ZD];
    __shared__ float qe[HD];
    __shared__ float ps[4][ZD];
    __shared__ float us[ZD];
    int t = threadIdx.x;
    int b = blockIdx.x >> 4;
    int k0 = (blockIdx.x & 15) * 128;
    for (int i = t; i < ZD * ZD / 4; i += 256)
        ((float4*)Ms)[i] = ((const float4*)g_M)[i];
    qe[t] = g_qenc[b][t];
    __syncthreads();
    // u_b[e] = q_enc[b] . Wk_z[e], 4-way partial split over h
    {
        int e = t & 63, part = t >> 6;
        const float4* wr = (const float4*)(wk + (size_t)(HD + e) * HD) + part * 16;
        const float4* qr = (const float4*)qe + part * 16;
        float pu = 0.f;
#pragma unroll
        for (int i = 0; i < 16; i++) {
            float4 w4 = wr[i], q4 = qr[i];
            pu += q4.x * w4.x + q4.y * w4.y + q4.z * w4.z + q4.w * w4.w;
        }
        ps[part][e] = pu;
    }
    __syncthreads();
    if (t < ZD) us[t] = (ps[0][t] + ps[1][t]) + (ps[2][t] + ps[3][t]);
    __syncthreads();

    int key = k0 + (t & 127);
    int dh = t >> 7;                 // 0/1 -> d range [dh*32, dh*32+32)
    const float4* zp4 = (const float4*)(z + ((size_t)b * SL + key) * ZD);
    float zr[ZD];
#pragma unroll
    for (int i = 0; i < ZD / 4; i++) {
        float4 v = zp4[i];
        zr[4 * i + 0] = v.x; zr[4 * i + 1] = v.y;
        zr[4 * i + 2] = v.z; zr[4 * i + 3] = v.w;
    }
    const float inv_t = 0.0625f;
    if (dh == 0) {
        float cacc = 0.f;
#pragma unroll
        for (int e = 0; e < ZD; e++) cacc += zr[e] * us[e];
        g_c[b][key] = cacc * inv_t;
    }
    float* wt = g_wT + (size_t)b * ZD * SL;
#pragma unroll
    for (int d4 = dh * 8; d4 < dh * 8 + 8; d4++) {
        float a0 = 0.f, a1 = 0.f, a2 = 0.f, a3 = 0.f;
#pragma unroll
        for (int e4 = 0; e4 < ZD / 4; e4++) {
            float4 m0 = ((const float4*)&Ms[4 * d4 + 0][0])[e4];
            float4 m1 = ((const float4*)&Ms[4 * d4 + 1][0])[e4];
            float4 m2 = ((const float4*)&Ms[4 * d4 + 2][0])[e4];
            float4 m3 = ((const float4*)&Ms[4 * d4 + 3][0])[e4];
            float z0 = zr[4 * e4 + 0], z1 = zr[4 * e4 + 1];
            float z2 = zr[4 * e4 + 2], z3 = zr[4 * e4 + 3];
            a0 += m0.x * z0 + m0.y * z1 + m0.z * z2 + m0.w * z3;
            a1 += m1.x * z0 + m1.y * z1 + m1.z * z2 + m1.w * z3;
            a2 += m2.x * z0 + m2.y * z1 + m2.z * z2 + m2.w * z3;
            a3 += m3.x * z0 + m3.y * z1 + m3.z * z2 + m3.w * z3;
        }
        wt[(size_t)(4 * d4 + 0) * SL + key] = a0 * inv_t;
        wt[(size_t)(4 * d4 + 1) * SL + key] = a1 * inv_t;
        wt[(size_t)(4 * d4 + 2) * SL + key] = a2 * inv_t;
        wt[(size_t)(4 * d4 + 3) * SL + key] = a3 * inv_t;
    }
}

// =================== kernel 3: scores + softmax + output ===================
struct __align__(16) AttnSmem {
    float  sc[QT][SL];        // 131072 B: scores -> exp values
    float  w[2][ES][KC];      //  65536 B: w stages; later wv slice [64][256]
    float2 zq2[QT][ZD];       //   8192 B
    float  yT[ZD][QT];        //   4096 B
    float  pv[QT][CAP];       //   8192 B
    int    kv[QT][CAP];       //   8192 B
    int    cnt[QT];
};

__global__ void __launch_bounds__(512, 1)
k_attn(const float* __restrict__ z, const float* __restrict__ wv,
       const int* __restrict__ mask, float* __restrict__ outp,
       float* __restrict__ attnp) {
    extern __shared__ char smraw[];
    AttnSmem& s = *reinterpret_cast<AttnSmem*>(smraw);
    int t = threadIdx.x;
    int b = blockIdx.x >> 7;
    int q0 = (blockIdx.x & 127) * QT;

    const float* gwT = g_wT + (size_t)b * ZD * SL;

    // fill duplicated zq pairs [QT][ZD]
#pragma unroll
    for (int i = 0; i < 2; i++) {
        int idx = t + i * 512;
        int q = idx >> 6, e = idx & 63;
        float v = z[((size_t)b * SL + q0 + q) * ZD + e];
        s.zq2[q][e] = make_float2(v, v);
    }

    // prefetch stage 0
#pragma unroll
    for (int i = 0; i < 4; i++) {
        int idx = t + i * 512;
        int el = idx >> 8, f4 = idx & 255;
        uint32_t sa = (uint32_t)__cvta_generic_to_shared(&s.w[0][el][f4 * 4]);
        cp16(sa, gwT + (size_t)el * SL + f4 * 4);
    }
    cp_commit();

    int kq = t & 255, qg = t >> 8;
    int kk = kq * 4;
    ull acc2[8][2];

    // ---- pipelined score GEMM over 16 stages (2 chunks x 8 e-slices) ----
    for (int st = 0; st < NST; st++) {
        cp_wait0();
        __syncthreads();

        int nst = st + 1;
        if (nst < NST) {
            int nch = nst >> 3, nes = nst & 7;
#pragma unroll
            for (int i = 0; i < 4; i++) {
                int idx = t + i * 512;
                int el = idx >> 8, f4 = idx & 255;
                uint32_t sa = (uint32_t)__cvta_generic_to_shared(
                    &s.w[nst & 1][el][f4 * 4]);
                cp16(sa, gwT + (size_t)(nes * ES + el) * SL + nch * KC + f4 * 4);
            }
            cp_commit();
        }

        int ch = st >> 3, es = st & 7, buf = st & 1;
        int k0 = ch * KC;
        if (es == 0) {
            ulonglong2 cv2 = *((const ulonglong2*)&g_c[b][k0 + kk]);
#pragma unroll
            for (int i = 0; i < 8; i++) { acc2[i][0] = cv2.x; acc2[i][1] = cv2.y; }
        }
        int eb = es * ES;
#pragma unroll
        for (int e4 = 0; e4 < 2; e4++) {
            const int el = e4 * 4;
            ulonglong2 b0 = *(const ulonglong2*)&s.w[buf][el + 0][kk];
            ulonglong2 b1 = *(const ulonglong2*)&s.w[buf][el + 1][kk];
            ulonglong2 b2 = *(const ulonglong2*)&s.w[buf][el + 2][kk];
            ulonglong2 b3 = *(const ulonglong2*)&s.w[buf][el + 3][kk];
#pragma unroll
            for (int i = 0; i < 8; i++) {
                const ulonglong2* ap =
                    (const ulonglong2*)&s.zq2[8 * qg + i][eb + el];
                ulonglong2 aA = ap[0], aB = ap[1];
                fma2(acc2[i][0], aA.x, b0.x); fma2(acc2[i][1], aA.x, b0.y);
                fma2(acc2[i][0], aA.y, b1.x); fma2(acc2[i][1], aA.y, b1.y);
                fma2(acc2[i][0], aB.x, b2.x); fma2(acc2[i][1], aB.x, b2.y);
                fma2(acc2[i][0], aB.y, b3.x); fma2(acc2[i][1], aB.y, b3.y);
            }
        }
        if (es == 7) {
#pragma unroll
            for (int i = 0; i < 8; i++)
                *((ulonglong2*)&s.sc[8 * qg + i][k0 + kk]) =
                    make_ulonglong2(acc2[i][0], acc2[i][1]);
        }
    }
    __syncthreads();

    // ---- stage wv slice [64][256] into freed w buffer; overlaps softmax ----
    float* wvs = &s.w[0][0][0];
#pragma unroll
    for (int i = 0; i < 8; i++) {
        int idx = t + i * 512;              // 0..4095 float4s
        int el = idx >> 6, f4 = idx & 63;
        uint32_t sa = (uint32_t)__cvta_generic_to_shared(wvs + (size_t)idx * 4);
        cp16(sa, wv + (size_t)(HD + el) * HD + f4 * 4);
    }
    cp_commit();

    // ---- per-row softmax: 16 warps, one row each ----
    int w_id = t >> 5, lane = t & 31;
    const float* zb = z + (size_t)b * SL * ZD;
    {
        int r = w_id;
        int msk = mask[b * SL + q0 + r];
        if (lane == 0) s.cnt[r] = 0;
        __syncwarp();

        float4* ap = attnp ? (float4*)(attnp + (size_t)(b * SL + q0 + r) * SL)
                           : (float4*)0;
        float y0 = 0.f, y1 = 0.f;
        if (msk == 0) {
            if (ap) {
                const float u = 1.0f / 2048.0f;
                float4 u4 = make_float4(u, u, u, u);
#pragma unroll
                for (int i = 0; i < 16; i++) __stcs(&ap[i * 32 + lane], u4);
            }
            y0 = g_zsum[b][lane] * (1.0f / 2048.0f);
            y1 = g_zsum[b][lane + 32] * (1.0f / 2048.0f);
        } else {
            const float4* row4 = (const float4*)&s.sc[r][0];
            float4* row4w = (float4*)&s.sc[r][0];
            // sweep 1: row max
            float mx = -3.4e38f;
#pragma unroll
            for (int i = 0; i < 16; i++) {
                float4 v = row4[i * 32 + lane];
                mx = fmaxf(mx, fmaxf(fmaxf(v.x, v.y), fmaxf(v.z, v.w)));
            }
#pragma unroll
            for (int o = 16; o; o >>= 1) mx = fmaxf(mx, __shfl_xor_sync(~0u, mx, o));
            // sweep 2: exp + Z + list; dead windows -> direct zero store
            float Zp = 0.f;
            unsigned live = 0;
            float4 zero4 = make_float4(0.f, 0.f, 0.f, 0.f);
            for (int i = 0; i < 16; i++) {
                int idx = i * 32 + lane;
                float4 v = row4[idx];
                float d0 = v.x - mx, d1 = v.y - mx, d2 = v.z - mx, d3 = v.w - mx;
                float dm = fmaxf(fmaxf(d0, d1), fmaxf(d2, d3));
                unsigned bal = __ballot_sync(~0u, dm >= SKIP_T);
                if (bal == 0) {
                    if (ap) __stcs(&ap[idx], zero4);
                    continue;
                }
                live |= 1u << i;
                float p0 = __expf(d0), p1 = __expf(d1);
                float p2 = __expf(d2), p3 = __expf(d3);
                row4w[idx] = make_float4(p0, p1, p2, p3);
                Zp += (p0 + p1) + (p2 + p3);
                int kb = idx * 4;
                if (p0 > 0.f) { int p = atomicAdd(&s.cnt[r], 1); if (p < CAP) { s.kv[r][p] = kb + 0; s.pv[r][p] = p0; } }
                if (p1 > 0.f) { int p = atomicAdd(&s.cnt[r], 1); if (p < CAP) { s.kv[r][p] = kb + 1; s.pv[r][p] = p1; } }
                if (p2 > 0.f) { int p = atomicAdd(&s.cnt[r], 1); if (p < CAP) { s.kv[r][p] = kb + 2; s.pv[r][p] = p2; } }
                if (p3 > 0.f) { int p = atomicAdd(&s.cnt[r], 1); if (p < CAP) { s.kv[r][p] = kb + 3; s.pv[r][p] = p3; } }
            }
#pragma unroll
            for (int o = 16; o; o >>= 1) Zp += __shfl_xor_sync(~0u, Zp, o);
            float iz = 1.0f / Zp;
            // sweep 3: normalize + store only live windows
            if (ap) {
                unsigned lv = live;
                while (lv) {
                    int i = __ffs(lv) - 1;
                    lv &= lv - 1;
                    int idx = i * 32 + lane;
                    float4 p = row4[idx];
                    __stcs(&ap[idx],
                           make_float4(p.x * iz, p.y * iz, p.z * iz, p.w * iz));
                }
            }
            // y accumulation
            int cnt = s.cnt[r];
            if (cnt <= CAP) {
                for (int i = 0; i < cnt; i++) {
                    float a = s.pv[r][i] * iz;
                    int k = s.kv[r][i];
                    y0 += a * zb[(size_t)k * ZD + lane];
                    y1 += a * zb[(size_t)k * ZD + lane + 32];
                }
            } else {
                unsigned lv = live;
                while (lv) {
                    int i = __ffs(lv) - 1;
                    lv &= lv - 1;
                    for (int k = i * 128; k < i * 128 + 128; k++) {
                        float p = s.sc[r][k];
                        if (p != 0.f) {
                            float a = p * iz;
                            y0 += a * zb[(size_t)k * ZD + lane];
                            y1 += a * zb[(size_t)k * ZD + lane + 32];
                        }
                    }
                }
            }
        }
        s.yT[lane][r] = y0;
        s.yT[lane + 32][r] = y1;
    }
    cp_wait0();
    __syncthreads();

    // ---- output epilogue: packed f32x2, wv from smem ----
    if (outp) {
        int h = t & 255, qh = t >> 8;
        float ve = g_venc[b][h];
        ull ved = dup2(ve);
        ull acc[4];
#pragma unroll
        for (int j = 0; j < 4; j++) acc[j] = ved;
#pragma unroll 8
        for (int e = 0; e < ZD; e++) {
            float wvv = wvs[e * HD + h];
            ull wd = dup2(wvv);
            const ulonglong2* yr = ((const ulonglong2*)&s.yT[e][0]) + qh * 2;
            ulonglong2 ya = yr[0], yb2 = yr[1];
            fma2(acc[0], wd, ya.x);  fma2(acc[1], wd, ya.y);
            fma2(acc[2], wd, yb2.x); fma2(acc[3], wd, yb2.y);
        }
#pragma unroll
        for (int j = 0; j < 4; j++) {
            float lo, hi;
            unpack2(lo, hi, acc[j]);
            outp[((size_t)b * SL + q0 + qh * 8 + 2 * j + 0) * HD + h] = lo;
            outp[((size_t)b * SL + q0 + qh * 8 + 2 * j + 1) * HD + h] = hi;
        }
    }
}

// ============================== launch =====================================
extern "C" void kernel_launch(void* const* d_in, const int* in_sizes, int n_in,
                              void* d_out, int out_size) {
    const float* ehs  = (const float*)d_in[0];
    // d_in[1] = decoder_hidden_state (unused by reference)
    const float* z    = (const float*)d_in[2];
    const int*   mask = (const int*)d_in[3];
    const float* wq   = (const float*)d_in[4];
    const float* wk   = (const float*)d_in[5];
    const float* wv   = (const float*)d_in[6];

    const long OUT_N = (long)BB * SL * HD;   //  4,194,304
    const long ATT_N = (long)BB * SL * SL;   // 33,554,432
    float* o = (float*)d_out;
    float* outp = nullptr;
    float* attnp = nullptr;
    if ((long)out_size >= OUT_N + ATT_N) { outp = o; attnp = o + OUT_N; }
    else if ((long)out_size == ATT_N)    { attnp = o; }
    else                                 { outp = o; }

    const int PREP_SMEM = (ZD + 16) * KZP * 4;   // 83200 B (M part dominates)

    static int attr_set = 0;
    if (!attr_set) {
        cudaFuncSetAttribute(k_attn, cudaFuncAttributeMaxDynamicSharedMemorySize,
                             (int)sizeof(AttnSmem));
        cudaFuncSetAttribute(k_prep, cudaFuncAttributeMaxDynamicSharedMemorySize,
                             PREP_SMEM);
        attr_set = 1;
    }

    k_prep<<<BB + 4, 256, PREP_SMEM>>>(ehs, z, wq, wk, wv);
    k_wc<<<128, 256>>>(z, wk);
    k_attn<<<BB * (SL / QT), 512, sizeof(AttnSmem)>>>(z, wv, mask, outp, attnp);
}

// round 8
// speedup vs baseline: 2.0346x; 1.1527x over previous
#include <cuda_runtime.h>
#include <math.h>
#include <stdint.h>
#include <stddef.h>

// ---- problem constants ----
#define HD  256      // HIDDEN_DIM
#define ZD  64       // Z_DIM
#define BB  8        // batch
#define SL  2048     // SRC_LEN
#define QT  16       // queries per block in k_attn
#define KC  1024     // key chunk in k_attn
#define ES  8        // e-rows per pipeline stage
#define NST 16       // stages = (SL/KC) * (ZD/ES)
#define CAP 128      // per-row nonzero-attn list capacity
#define SKIP_T (-88.0f)
#define KZP 260      // padded smem row (floats) for prep M-part

typedef unsigned long long ull;

// ---- device scratch (no allocation allowed) ----
__device__ float g_venc[BB][HD];
__device__ float g_qenc[BB][HD];
__device__ float g_zsum[BB][ZD];
__device__ float g_M[ZD][ZD];
__device__ float g_wT[BB * ZD * SL]; // [b][d][key], w = (M z_k)/16
__device__ float g_c[BB][SL];        // c_k = (u_b . z_k)/16

// ---- packed fp32x2 helpers ----
__device__ __forceinline__ void fma2(ull& d, ull a, ull b) {
    asm("fma.rn.f32x2 %0, %1, %2, %0;" : "+l"(d) : "l"(a), "l"(b));
}
__device__ __forceinline__ ull dup2(float x) {
    ull r;
    asm("mov.b64 %0, {%1, %1};" : "=l"(r) : "f"(x));
    return r;
}
__device__ __forceinline__ void unpack2(float& lo, float& hi, ull v) {
    asm("mov.b64 {%0, %1}, %2;" : "=f"(lo), "=f"(hi) : "l"(v));
}

// ---- cp.async helpers ----
__device__ __forceinline__ void cp16(uint32_t saddr, const void* gaddr) {
    asm volatile("cp.async.cg.shared.global [%0], [%1], 16;"
                 :: "r"(saddr), "l"(gaddr));
}
__device__ __forceinline__ void cp_commit() {
    asm volatile("cp.async.commit_group;");
}
__device__ __forceinline__ void cp_wait0() {
    asm volatile("cp.async.wait_group 0;");
}

// ====== kernel 1 (fused): blocks 0..7 per-batch consts; 8..11 M tiles ======
// 1024 threads/block; latency chains split 4-16x vs prior round
__global__ void __launch_bounds__(1024, 1)
k_prep(const float* __restrict__ ehs,
       const float* __restrict__ z,
       const float* __restrict__ wq,
       const float* __restrict__ wk,
       const float* __restrict__ wv) {
    extern __shared__ char smraw[];
    int t = threadIdx.x;
    if (blockIdx.x < BB) {
        float* enc = (float*)smraw;           // [HD]
        float* pq  = enc + HD;                // [4][HD]
        float* pvv = pq + 4 * HD;             // [4][HD]
        float* zs  = pvv + 4 * HD;            // [16][ZD]
        int b = blockIdx.x;
        if (t < HD) enc[t] = ehs[b * HD + t] + ehs[BB * HD + b * HD + t];
        __syncthreads();
        // qenc/venc with 4-way d-split
        {
            int h = t & 255, p = t >> 8;       // p in 0..3
            float aq = 0.f, av = 0.f;
#pragma unroll 8
            for (int d = p * 64; d < p * 64 + 64; d++) {
                float ev = enc[d];
                aq += ev * wq[d * HD + h];
                av += ev * wv[d * HD + h];
            }
            pq[p * HD + h] = aq;
            pvv[p * HD + h] = av;
        }
        // zsum with 16-way key split
        {
            int e = t & 63, p = t >> 6;        // p in 0..15
            const float* zp = z + (size_t)b * SL * ZD;
            float sm = 0.f;
#pragma unroll 8
            for (int k = p * 128; k < p * 128 + 128; k++)
                sm += zp[(size_t)k * ZD + e];
            zs[p * ZD + e] = sm;
        }
        __syncthreads();
        if (t < HD) {
            g_qenc[b][t] = (pq[0 * HD + t] + pq[1 * HD + t]) +
                           (pq[2 * HD + t] + pq[3 * HD + t]);
            g_venc[b][t] = (pvv[0 * HD + t] + pvv[1 * HD + t]) +
                           (pvv[2 * HD + t] + pvv[3 * HD + t]);
        } else if (t < HD + ZD) {
            int e = t - HD;
            float sm = 0.f;
#pragma unroll
            for (int p = 0; p < 16; p++) sm += zs[p * ZD + e];
            g_zsum[b][e] = sm;
        }
    } else {
        // M[d][e] = sum_h Wq_z[d,h] * Wk_z[e,h], smem-staged, 1 row/thread
        float (*kz)[KZP] = (float (*)[KZP])smraw;                  // [ZD][KZP]
        float (*qz)[KZP] = (float (*)[KZP])(smraw + ZD * KZP * 4); // [16][KZP]
        int i = blockIdx.x - BB;
        // load Wk_z: 4096 float4 over 1024 threads
#pragma unroll
        for (int r = 0; r < 4; r++) {
            int idx = t + r * 1024;
            int e = idx >> 6, f4 = idx & 63;
            float4 v = *((const float4*)(wk + (size_t)(HD + e) * HD) + f4);
            *((float4*)&kz[e][0] + f4) = v;
        }
        // load 16 Wq_z rows: 1024 float4
        {
            int dl = t >> 6, f4 = t & 63;
            float4 v = *((const float4*)(wq + (size_t)(HD + i * 16 + dl) * HD) + f4);
            *((float4*)&qz[dl][0] + f4) = v;
        }
        __syncthreads();
        int e = t & 63, jg = t >> 6;          // jg in 0..15, 1 row each
        float a0 = 0.f;
#pragma unroll 8
        for (int h4 = 0; h4 < HD / 4; h4++) {
            float4 kv = *((const float4*)&kz[e][0] + h4);
            float4 q0 = *((const float4*)&qz[jg][0] + h4);
            a0 += q0.x * kv.x + q0.y * kv.y + q0.z * kv.z + q0.w * kv.w;
        }
        g_M[i * 16 + jg][e] = a0;
    }
}

// ===== kernel 2: wT[b,d,k] = (M z_k)[d]/16, c[b,k] = (u_b.z_k)/16 ==========
// grid = 128 blocks * 256 threads; 128 keys/block, d split across 2 halves
__global__ void k_wc(const float* __restrict__ z,
                     const float* __restrict__ wk) {
    __shared__ float Ms[ZD][ZD];
    __shared__ float qe[HD];
    __shared__ float ps[4][ZD];
    __shared__ float us[ZD];
    int t = threadIdx.x;
    int b = blockIdx.x >> 4;
    int k0 = (blockIdx.x & 15) * 128;
    for (int i = t; i < ZD * ZD / 4; i += 256)
        ((float4*)Ms)[i] = ((const float4*)g_M)[i];
    qe[t] = g_qenc[b][t];
    __syncthreads();
    // u_b[e] = q_enc[b] . Wk_z[e], 4-way partial split over h
    {
        int e = t & 63, part = t >> 6;
        const float4* wr = (const float4*)(wk + (size_t)(HD + e) * HD) + part * 16;
        const float4* qr = (const float4*)qe + part * 16;
        float pu = 0.f;
#pragma unroll
        for (int i = 0; i < 16; i++) {
            float4 w4 = wr[i], q4 = qr[i];
            pu += q4.x * w4.x + q4.y * w4.y + q4.z * w4.z + q4.w * w4.w;
        }
        ps[part][e] = pu;
    }
    __syncthreads();
    if (t < ZD) us[t] = (ps[0][t] + ps[1][t]) + (ps[2][t] + ps[3][t]);
    __syncthreads();

    int key = k0 + (t & 127);
    int dh = t >> 7;                 // 0/1 -> d range [dh*32, dh*32+32)
    const float4* zp4 = (const float4*)(z + ((size_t)b * SL + key) * ZD);
    float zr[ZD];
#pragma unroll
    for (int i = 0; i < ZD / 4; i++) {
        float4 v = zp4[i];
        zr[4 * i + 0] = v.x; zr[4 * i + 1] = v.y;
        zr[4 * i + 2] = v.z; zr[4 * i + 3] = v.w;
    }
    const float inv_t = 0.0625f;
    if (dh == 0) {
        float cacc = 0.f;
#pragma unroll
        for (int e = 0; e < ZD; e++) cacc += zr[e] * us[e];
        g_c[b][key] = cacc * inv_t;
    }
    float* wt = g_wT + (size_t)b * ZD * SL;
#pragma unroll
    for (int d4 = dh * 8; d4 < dh * 8 + 8; d4++) {
        float a0 = 0.f, a1 = 0.f, a2 = 0.f, a3 = 0.f;
#pragma unroll
        for (int e4 = 0; e4 < ZD / 4; e4++) {
            float4 m0 = ((const float4*)&Ms[4 * d4 + 0][0])[e4];
            float4 m1 = ((const float4*)&Ms[4 * d4 + 1][0])[e4];
            float4 m2 = ((const float4*)&Ms[4 * d4 + 2][0])[e4];
            float4 m3 = ((const float4*)&Ms[4 * d4 + 3][0])[e4];
            float z0 = zr[4 * e4 + 0], z1 = zr[4 * e4 + 1];
            float z2 = zr[4 * e4 + 2], z3 = zr[4 * e4 + 3];
            a0 += m0.x * z0 + m0.y * z1 + m0.z * z2 + m0.w * z3;
            a1 += m1.x * z0 + m1.y * z1 + m1.z * z2 + m1.w * z3;
            a2 += m2.x * z0 + m2.y * z1 + m2.z * z2 + m2.w * z3;
            a3 += m3.x * z0 + m3.y * z1 + m3.z * z2 + m3.w * z3;
        }
        wt[(size_t)(4 * d4 + 0) * SL + key] = a0 * inv_t;
        wt[(size_t)(4 * d4 + 1) * SL + key] = a1 * inv_t;
        wt[(size_t)(4 * d4 + 2) * SL + key] = a2 * inv_t;
        wt[(size_t)(4 * d4 + 3) * SL + key] = a3 * inv_t;
    }
}

// =================== kernel 3: scores + softmax + output ===================
struct __align__(16) AttnSmem {
    float  sc[QT][SL];        // 131072 B: scores -> exp values
    float  w[2][ES][KC];      //  65536 B: w stages; later wv slice [64][256]
    float  zq[QT][ZD];        //   4096 B
    float  yT[ZD][QT];        //   4096 B
    float  pv[QT][CAP];       //   8192 B
    int    kv[QT][CAP];       //   8192 B
    int    cnt[QT];
};

__global__ void __launch_bounds__(512, 1)
k_attn(const float* __restrict__ z, const float* __restrict__ wv,
       const int* __restrict__ mask, float* __restrict__ outp,
       float* __restrict__ attnp) {
    extern __shared__ char smraw[];
    AttnSmem& s = *reinterpret_cast<AttnSmem*>(smraw);
    int t = threadIdx.x;
    int b = blockIdx.x >> 7;
    int q0 = (blockIdx.x & 127) * QT;

    const float* gwT = g_wT + (size_t)b * ZD * SL;

    // fill zq [QT][ZD]
#pragma unroll
    for (int i = 0; i < 2; i++) {
        int idx = t + i * 512;
        int q = idx >> 6, e = idx & 63;
        s.zq[q][e] = z[((size_t)b * SL + q0 + q) * ZD + e];
    }

    // prefetch stage 0
#pragma unroll
    for (int i = 0; i < 4; i++) {
        int idx = t + i * 512;
        int el = idx >> 8, f4 = idx & 255;
        uint32_t sa = (uint32_t)__cvta_generic_to_shared(&s.w[0][el][f4 * 4]);
        cp16(sa, gwT + (size_t)el * SL + f4 * 4);
    }
    cp_commit();

    int kq = t & 255, qg = t >> 8;
    int kk = kq * 4;
    ull acc2[8][2];

    // ---- pipelined score GEMM over 16 stages (2 chunks x 8 e-slices) ----
    for (int st = 0; st < NST; st++) {
        cp_wait0();
        __syncthreads();

        int nst = st + 1;
        if (nst < NST) {
            int nch = nst >> 3, nes = nst & 7;
#pragma unroll
            for (int i = 0; i < 4; i++) {
                int idx = t + i * 512;
                int el = idx >> 8, f4 = idx & 255;
                uint32_t sa = (uint32_t)__cvta_generic_to_shared(
                    &s.w[nst & 1][el][f4 * 4]);
                cp16(sa, gwT + (size_t)(nes * ES + el) * SL + nch * KC + f4 * 4);
            }
            cp_commit();
        }

        int ch = st >> 3, es = st & 7, buf = st & 1;
        int k0 = ch * KC;
        if (es == 0) {
            ulonglong2 cv2 = *((const ulonglong2*)&g_c[b][k0 + kk]);
#pragma unroll
            for (int i = 0; i < 8; i++) { acc2[i][0] = cv2.x; acc2[i][1] = cv2.y; }
        }
        int eb = es * ES;
#pragma unroll
        for (int e4 = 0; e4 < 2; e4++) {
            const int el = e4 * 4;
            ulonglong2 b0 = *(const ulonglong2*)&s.w[buf][el + 0][kk];
            ulonglong2 b1 = *(const ulonglong2*)&s.w[buf][el + 1][kk];
            ulonglong2 b2 = *(const ulonglong2*)&s.w[buf][el + 2][kk];
            ulonglong2 b3 = *(const ulonglong2*)&s.w[buf][el + 3][kk];
#pragma unroll
            for (int i = 0; i < 8; i++) {
                float4 a = *(const float4*)&s.zq[8 * qg + i][eb + el];
                ull ax = dup2(a.x), ay = dup2(a.y);
                ull az = dup2(a.z), aw = dup2(a.w);
                fma2(acc2[i][0], ax, b0.x); fma2(acc2[i][1], ax, b0.y);
                fma2(acc2[i][0], ay, b1.x); fma2(acc2[i][1], ay, b1.y);
                fma2(acc2[i][0], az, b2.x); fma2(acc2[i][1], az, b2.y);
                fma2(acc2[i][0], aw, b3.x); fma2(acc2[i][1], aw, b3.y);
            }
        }
        if (es == 7) {
#pragma unroll
            for (int i = 0; i < 8; i++)
                *((ulonglong2*)&s.sc[8 * qg + i][k0 + kk]) =
                    make_ulonglong2(acc2[i][0], acc2[i][1]);
        }
    }
    __syncthreads();

    // ---- stage wv slice [64][256] into freed w buffer; overlaps softmax ----
    float* wvs = &s.w[0][0][0];
#pragma unroll
    for (int i = 0; i < 8; i++) {
        int idx = t + i * 512;              // 0..4095 float4s
        int el = idx >> 6, f4 = idx & 63;
        uint32_t sa = (uint32_t)__cvta_generic_to_shared(wvs + (size_t)idx * 4);
        cp16(sa, wv + (size_t)(HD + el) * HD + f4 * 4);
    }
    cp_commit();

    // ---- per-row softmax: 16 warps, one row each ----
    int w_id = t >> 5, lane = t & 31;
    const float* zb = z + (size_t)b * SL * ZD;
    {
        int r = w_id;
        int msk = mask[b * SL + q0 + r];
        if (lane == 0) s.cnt[r] = 0;
        __syncwarp();

        float4* ap = attnp ? (float4*)(attnp + (size_t)(b * SL + q0 + r) * SL)
                           : (float4*)0;
        float y0 = 0.f, y1 = 0.f;
        if (msk == 0) {
            if (ap) {
                const float u = 1.0f / 2048.0f;
                float4 u4 = make_float4(u, u, u, u);
#pragma unroll
                for (int i = 0; i < 16; i++) __stcs(&ap[i * 32 + lane], u4);
            }
            y0 = g_zsum[b][lane] * (1.0f / 2048.0f);
            y1 = g_zsum[b][lane + 32] * (1.0f / 2048.0f);
        } else {
            const float4* row4 = (const float4*)&s.sc[r][0];
            float4* row4w = (float4*)&s.sc[r][0];
            // sweep 1: row max
            float mx = -3.4e38f;
#pragma unroll
            for (int i = 0; i < 16; i++) {
                float4 v = row4[i * 32 + lane];
                mx = fmaxf(mx, fmaxf(fmaxf(v.x, v.y), fmaxf(v.z, v.w)));
            }
#pragma unroll
            for (int o = 16; o; o >>= 1) mx = fmaxf(mx, __shfl_xor_sync(~0u, mx, o));
            // sweep 2: exp + Z + list; dead windows -> direct zero store
            float Zp = 0.f;
            unsigned live = 0;
            float4 zero4 = make_float4(0.f, 0.f, 0.f, 0.f);
            for (int i = 0; i < 16; i++) {
                int idx = i * 32 + lane;
                float4 v = row4[idx];
                float d0 = v.x - mx, d1 = v.y - mx, d2 = v.z - mx, d3 = v.w - mx;
                float dm = fmaxf(fmaxf(d0, d1), fmaxf(d2, d3));
                unsigned bal = __ballot_sync(~0u, dm >= SKIP_T);
                if (bal == 0) {
                    if (ap) __stcs(&ap[idx], zero4);
                    continue;
                }
                live |= 1u << i;
                float p0 = __expf(d0), p1 = __expf(d1);
                float p2 = __expf(d2), p3 = __expf(d3);
                row4w[idx] = make_float4(p0, p1, p2, p3);
                Zp += (p0 + p1) + (p2 + p3);
                int kb = idx * 4;
                if (p0 > 0.f) { int p = atomicAdd(&s.cnt[r], 1); if (p < CAP) { s.kv[r][p] = kb + 0; s.pv[r][p] = p0; } }
                if (p1 > 0.f) { int p = atomicAdd(&s.cnt[r], 1); if (p < CAP) { s.kv[r][p] = kb + 1; s.pv[r][p] = p1; } }
                if (p2 > 0.f) { int p = atomicAdd(&s.cnt[r], 1); if (p < CAP) { s.kv[r][p] = kb + 2; s.pv[r][p] = p2; } }
                if (p3 > 0.f) { int p = atomicAdd(&s.cnt[r], 1); if (p < CAP) { s.kv[r][p] = kb + 3; s.pv[r][p] = p3; } }
            }
#pragma unroll
            for (int o = 16; o; o >>= 1) Zp += __shfl_xor_sync(~0u, Zp, o);
            float iz = 1.0f / Zp;
            // sweep 3: normalize + store only live windows
            if (ap) {
                unsigned lv = live;
                while (lv) {
                    int i = __ffs(lv) - 1;
                    lv &= lv - 1;
                    int idx = i * 32 + lane;
                    float4 p = row4[idx];
                    __stcs(&ap[idx],
                           make_float4(p.x * iz, p.y * iz, p.z * iz, p.w * iz));
                }
            }
            // y accumulation
            int cnt = s.cnt[r];
            if (cnt <= CAP) {
                for (int i = 0; i < cnt; i++) {
                    float a = s.pv[r][i] * iz;
                    int k = s.kv[r][i];
                    y0 += a * zb[(size_t)k * ZD + lane];
                    y1 += a * zb[(size_t)k * ZD + lane + 32];
                }
            } else {
                unsigned lv = live;
                while (lv) {
                    int i = __ffs(lv) - 1;
                    lv &= lv - 1;
                    for (int k = i * 128; k < i * 128 + 128; k++) {
                        float p = s.sc[r][k];
                        if (p != 0.f) {
                            float a = p * iz;
                            y0 += a * zb[(size_t)k * ZD + lane];
                            y1 += a * zb[(size_t)k * ZD + lane + 32];
                        }
                    }
                }
            }
        }
        s.yT[lane][r] = y0;
        s.yT[lane + 32][r] = y1;
    }
    cp_wait0();
    __syncthreads();

    // ---- output epilogue: packed f32x2, wv from smem ----
    if (outp) {
        int h = t & 255, qh = t >> 8;
        float ve = g_venc[b][h];
        ull ved = dup2(ve);
        ull acc[4];
#pragma unroll
        for (int j = 0; j < 4; j++) acc[j] = ved;
#pragma unroll 8
        for (int e = 0; e < ZD; e++) {
            float wvv = wvs[e * HD + h];
            ull wd = dup2(wvv);
            const ulonglong2* yr = ((const ulonglong2*)&s.yT[e][0]) + qh * 2;
            ulonglong2 ya = yr[0], yb2 = yr[1];
            fma2(acc[0], wd, ya.x);  fma2(acc[1], wd, ya.y);
            fma2(acc[2], wd, yb2.x); fma2(acc[3], wd, yb2.y);
        }
#pragma unroll
        for (int j = 0; j < 4; j++) {
            float lo, hi;
            unpack2(lo, hi, acc[j]);
            outp[((size_t)b * SL + q0 + qh * 8 + 2 * j + 0) * HD + h] = lo;
            outp[((size_t)b * SL + q0 + qh * 8 + 2 * j + 1) * HD + h] = hi;
        }
    }
}

// ============================== launch =====================================
extern "C" void kernel_launch(void* const* d_in, const int* in_sizes, int n_in,
                              void* d_out, int out_size) {
    const float* ehs  = (const float*)d_in[0];
    // d_in[1] = decoder_hidden_state (unused by reference)
    const float* z    = (const float*)d_in[2];
    const int*   mask = (const int*)d_in[3];
    const float* wq   = (const float*)d_in[4];
    const float* wk   = (const float*)d_in[5];
    const float* wv   = (const float*)d_in[6];

    const long OUT_N = (long)BB * SL * HD;   //  4,194,304
    const long ATT_N = (long)BB * SL * SL;   // 33,554,432
    float* o = (float*)d_out;
    float* outp = nullptr;
    float* attnp = nullptr;
    if ((long)out_size >= OUT_N + ATT_N) { outp = o; attnp = o + OUT_N; }
    else if ((long)out_size == ATT_N)    { attnp = o; }
    else                                 { outp = o; }

    const int PREP_SMEM = (ZD + 16) * KZP * 4;   // 83200 B (M part dominates)

    static int attr_set = 0;
    if (!attr_set) {
        cudaFuncSetAttribute(k_attn, cudaFuncAttributeMaxDynamicSharedMemorySize,
                             (int)sizeof(AttnSmem));
        cudaFuncSetAttribute(k_prep, cudaFuncAttributeMaxDynamicSharedMemorySize,
                             PREP_SMEM);
        attr_set = 1;
    }

    k_prep<<<BB + 4, 1024, PREP_SMEM>>>(ehs, z, wq, wk, wv);
    k_wc<<<128, 256>>>(z, wk);
    k_attn<<<BB * (SL / QT), 512, sizeof(AttnSmem)>>>(z, wv, mask, outp, attnp);
}